// round 1
// baseline (speedup 1.0000x reference)
#include <cuda_runtime.h>
#include <math.h>

// Problem constants
#define B_ 32
#define S_ 64
#define H_ 8
#define E_ 1024
#define HE_ 8192          // H*E
#define M_ 2048           // B*S

// Scratch buffers (allocation-free rule: __device__ globals)
__device__ float g_q[B_ * H_ * S_ * E_];
__device__ float g_k[B_ * H_ * S_ * E_];
__device__ float g_v[B_ * H_ * S_ * E_];
__device__ float g_y[B_ * S_ * HE_];

// ---------------------------------------------------------------------------
// GEMM 1: C = x @ W^T, epilogue: * mask[b,e] * scale, output layout (B,H,S,E)
// x: (2048, 1024) row-major, W: (8192, 1024) row-major (both K-contiguous: NT)
// Tile: 128x128x16, 256 threads, 8x8 per-thread microtile.
// ---------------------------------------------------------------------------
__global__ void __launch_bounds__(256) gemm_qkv_kernel(
    const float* __restrict__ A, const float* __restrict__ W,
    const float* __restrict__ mask, float* __restrict__ out, float scale)
{
    const int K = E_;
    __shared__ __align__(16) float As[16][132];
    __shared__ __align__(16) float Bs[16][132];

    int tid = threadIdx.x;
    int m0 = blockIdx.y * 128;
    int n0 = blockIdx.x * 128;

    int lr = tid >> 2;          // 0..63 (row within half-tile)
    int lc = (tid & 3) << 2;    // k offset {0,4,8,12}
    int tm = (tid >> 4) << 3;   // microtile row base
    int tn = (tid & 15) << 3;   // microtile col base

    float acc[8][8];
#pragma unroll
    for (int i = 0; i < 8; i++)
#pragma unroll
        for (int j = 0; j < 8; j++) acc[i][j] = 0.0f;

    const float* Ap = A + (size_t)(m0 + lr) * K + lc;
    const float* Wp = W + (size_t)(n0 + lr) * K + lc;

    for (int kt = 0; kt < K; kt += 16) {
#pragma unroll
        for (int p = 0; p < 2; p++) {
            int r = lr + p * 64;
            float4 va = *(const float4*)(Ap + (size_t)p * 64 * K + kt);
            As[lc + 0][r] = va.x; As[lc + 1][r] = va.y;
            As[lc + 2][r] = va.z; As[lc + 3][r] = va.w;
            float4 vb = *(const float4*)(Wp + (size_t)p * 64 * K + kt);
            Bs[lc + 0][r] = vb.x; Bs[lc + 1][r] = vb.y;
            Bs[lc + 2][r] = vb.z; Bs[lc + 3][r] = vb.w;
        }
        __syncthreads();
#pragma unroll
        for (int kk = 0; kk < 16; kk++) {
            float a[8], b[8];
            float4 t;
            t = *(const float4*)&As[kk][tm];     a[0]=t.x; a[1]=t.y; a[2]=t.z; a[3]=t.w;
            t = *(const float4*)&As[kk][tm + 4]; a[4]=t.x; a[5]=t.y; a[6]=t.z; a[7]=t.w;
            t = *(const float4*)&Bs[kk][tn];     b[0]=t.x; b[1]=t.y; b[2]=t.z; b[3]=t.w;
            t = *(const float4*)&Bs[kk][tn + 4]; b[4]=t.x; b[5]=t.y; b[6]=t.z; b[7]=t.w;
#pragma unroll
            for (int i = 0; i < 8; i++)
#pragma unroll
                for (int j = 0; j < 8; j++)
                    acc[i][j] = fmaf(a[i], b[j], acc[i][j]);
        }
        __syncthreads();
    }

    // Epilogue: out[((b*H + h)*S + s)*E + e] = acc * mask[b*E + e] * scale
#pragma unroll
    for (int i = 0; i < 8; i++) {
        int m = m0 + tm + i;
        int b = m >> 6;       // /S_
        int s = m & 63;
#pragma unroll
        for (int j = 0; j < 8; j++) {
            int n = n0 + tn + j;
            int h = n >> 10;  // /E_
            int e = n & 1023;
            out[(size_t)((b * H_ + h) * S_ + s) * E_ + e] =
                acc[i][j] * mask[b * E_ + e] * scale;
        }
    }
}

// ---------------------------------------------------------------------------
// Attention: one block per (b,h). S=64, E=1024.
// Phase 1: logits(64x64) = q @ k^T over E (chunks of 32 in smem, transposed)
// Softmax rows in-block. Phase 2: y(64x1024) = a @ v (e-chunks of 64).
// ---------------------------------------------------------------------------
__global__ void __launch_bounds__(256) attn_kernel(
    const float* __restrict__ q, const float* __restrict__ k,
    const float* __restrict__ v, float* __restrict__ y)
{
    int h = blockIdx.x;
    int b = blockIdx.y;
    const float* qb = q + (size_t)((b * H_ + h) * S_) * E_;
    const float* kb = k + (size_t)((b * H_ + h) * S_) * E_;
    const float* vb = v + (size_t)((b * H_ + h) * S_) * E_;
    float* yb = y + (size_t)(b * S_) * HE_ + h * E_;

    // phase1: sQ[32][68] + sK[32][68] (transposed chunks); phase2: reuse as sV[64][68]
    __shared__ __align__(16) float sQK[2 * 32 * 68];
    __shared__ __align__(16) float sL[64][68];

    int tid = threadIdx.x;
    int ty = tid >> 4;          // 0..15
    int tx = tid & 15;          // 0..15
    int r0 = ty * 4;
    int c0 = tx * 4;

    float* sQ = sQK;
    float* sK = sQK + 32 * 68;

    float acc[4][4];
#pragma unroll
    for (int i = 0; i < 4; i++)
#pragma unroll
        for (int j = 0; j < 4; j++) acc[i][j] = 0.0f;

    // ---- Phase 1: logits ----
    for (int kc = 0; kc < E_; kc += 32) {
#pragma unroll
        for (int l = 0; l < 2; l++) {
            int id = tid * 2 + l;           // 0..511
            int r = id >> 3;                // 0..63
            int cc = (id & 7) * 4;          // 0..28
            float4 qv = *(const float4*)&qb[(size_t)r * E_ + kc + cc];
            sQ[(cc + 0) * 68 + r] = qv.x; sQ[(cc + 1) * 68 + r] = qv.y;
            sQ[(cc + 2) * 68 + r] = qv.z; sQ[(cc + 3) * 68 + r] = qv.w;
            float4 kv = *(const float4*)&kb[(size_t)r * E_ + kc + cc];
            sK[(cc + 0) * 68 + r] = kv.x; sK[(cc + 1) * 68 + r] = kv.y;
            sK[(cc + 2) * 68 + r] = kv.z; sK[(cc + 3) * 68 + r] = kv.w;
        }
        __syncthreads();
#pragma unroll
        for (int kk = 0; kk < 32; kk++) {
            float4 av = *(const float4*)&sQ[kk * 68 + r0];
            float4 bv = *(const float4*)&sK[kk * 68 + c0];
            float a[4] = {av.x, av.y, av.z, av.w};
            float bbv[4] = {bv.x, bv.y, bv.z, bv.w};
#pragma unroll
            for (int i = 0; i < 4; i++)
#pragma unroll
                for (int j = 0; j < 4; j++)
                    acc[i][j] = fmaf(a[i], bbv[j], acc[i][j]);
        }
        __syncthreads();
    }

#pragma unroll
    for (int i = 0; i < 4; i++)
#pragma unroll
        for (int j = 0; j < 4; j++)
            sL[r0 + i][c0 + j] = acc[i][j];
    __syncthreads();

    // ---- Softmax: row = tid/4, 4 threads per row, 16 cols each ----
    {
        int row = tid >> 2;
        int q4 = tid & 3;
        int cbase = q4 * 16;
        float mx = -1e30f;
#pragma unroll
        for (int c = 0; c < 16; c++) mx = fmaxf(mx, sL[row][cbase + c]);
        mx = fmaxf(mx, __shfl_xor_sync(0xffffffffu, mx, 1));
        mx = fmaxf(mx, __shfl_xor_sync(0xffffffffu, mx, 2));
        float sum = 0.0f;
#pragma unroll
        for (int c = 0; c < 16; c++) {
            float ev = __expf(sL[row][cbase + c] - mx);
            sL[row][cbase + c] = ev;
            sum += ev;
        }
        sum += __shfl_xor_sync(0xffffffffu, sum, 1);
        sum += __shfl_xor_sync(0xffffffffu, sum, 2);
        float inv = 1.0f / sum;
#pragma unroll
        for (int c = 0; c < 16; c++) sL[row][cbase + c] *= inv;
    }
    __syncthreads();

    // ---- Phase 2: y = a @ v, e-chunks of 64 ----
    float* sV = sQK;   // reuse as [64][68]
    for (int ec = 0; ec < E_; ec += 64) {
#pragma unroll
        for (int l = 0; l < 4; l++) {
            int id = tid * 4 + l;           // 0..1023
            int r = id >> 4;                // 0..63
            int cc = (id & 15) * 4;         // 0..60
            float4 vv = *(const float4*)&vb[(size_t)r * E_ + ec + cc];
            sV[r * 68 + cc + 0] = vv.x; sV[r * 68 + cc + 1] = vv.y;
            sV[r * 68 + cc + 2] = vv.z; sV[r * 68 + cc + 3] = vv.w;
        }
        __syncthreads();
        float o[4][4];
#pragma unroll
        for (int i = 0; i < 4; i++)
#pragma unroll
            for (int j = 0; j < 4; j++) o[i][j] = 0.0f;
#pragma unroll
        for (int m = 0; m < 64; m++) {
            float4 bv = *(const float4*)&sV[m * 68 + c0];
            float bbv[4] = {bv.x, bv.y, bv.z, bv.w};
            float a0 = sL[r0 + 0][m];
            float a1 = sL[r0 + 1][m];
            float a2 = sL[r0 + 2][m];
            float a3 = sL[r0 + 3][m];
#pragma unroll
            for (int j = 0; j < 4; j++) {
                o[0][j] = fmaf(a0, bbv[j], o[0][j]);
                o[1][j] = fmaf(a1, bbv[j], o[1][j]);
                o[2][j] = fmaf(a2, bbv[j], o[2][j]);
                o[3][j] = fmaf(a3, bbv[j], o[3][j]);
            }
        }
#pragma unroll
        for (int i = 0; i < 4; i++) {
            float4 wv = make_float4(o[i][0], o[i][1], o[i][2], o[i][3]);
            *(float4*)&yb[(size_t)(r0 + i) * HE_ + ec + c0] = wv;
        }
        __syncthreads();
    }
}

// ---------------------------------------------------------------------------
// GEMM 2: out = (y @ Wo^T + bo) * mask
// y: (2048, 8192) row-major, Wo: (1024, 8192) row-major (NT)
// ---------------------------------------------------------------------------
__global__ void __launch_bounds__(256) gemm_out_kernel(
    const float* __restrict__ A, const float* __restrict__ W,
    const float* __restrict__ bo, const float* __restrict__ mask,
    float* __restrict__ out)
{
    const int K = HE_;
    __shared__ __align__(16) float As[16][132];
    __shared__ __align__(16) float Bs[16][132];

    int tid = threadIdx.x;
    int m0 = blockIdx.y * 128;
    int n0 = blockIdx.x * 128;

    int lr = tid >> 2;
    int lc = (tid & 3) << 2;
    int tm = (tid >> 4) << 3;
    int tn = (tid & 15) << 3;

    float acc[8][8];
#pragma unroll
    for (int i = 0; i < 8; i++)
#pragma unroll
        for (int j = 0; j < 8; j++) acc[i][j] = 0.0f;

    const float* Ap = A + (size_t)(m0 + lr) * K + lc;
    const float* Wp = W + (size_t)(n0 + lr) * K + lc;

    for (int kt = 0; kt < K; kt += 16) {
#pragma unroll
        for (int p = 0; p < 2; p++) {
            int r = lr + p * 64;
            float4 va = *(const float4*)(Ap + (size_t)p * 64 * K + kt);
            As[lc + 0][r] = va.x; As[lc + 1][r] = va.y;
            As[lc + 2][r] = va.z; As[lc + 3][r] = va.w;
            float4 vb = *(const float4*)(Wp + (size_t)p * 64 * K + kt);
            Bs[lc + 0][r] = vb.x; Bs[lc + 1][r] = vb.y;
            Bs[lc + 2][r] = vb.z; Bs[lc + 3][r] = vb.w;
        }
        __syncthreads();
#pragma unroll
        for (int kk = 0; kk < 16; kk++) {
            float a[8], b[8];
            float4 t;
            t = *(const float4*)&As[kk][tm];     a[0]=t.x; a[1]=t.y; a[2]=t.z; a[3]=t.w;
            t = *(const float4*)&As[kk][tm + 4]; a[4]=t.x; a[5]=t.y; a[6]=t.z; a[7]=t.w;
            t = *(const float4*)&Bs[kk][tn];     b[0]=t.x; b[1]=t.y; b[2]=t.z; b[3]=t.w;
            t = *(const float4*)&Bs[kk][tn + 4]; b[4]=t.x; b[5]=t.y; b[6]=t.z; b[7]=t.w;
#pragma unroll
            for (int i = 0; i < 8; i++)
#pragma unroll
                for (int j = 0; j < 8; j++)
                    acc[i][j] = fmaf(a[i], b[j], acc[i][j]);
        }
        __syncthreads();
    }

#pragma unroll
    for (int i = 0; i < 8; i++) {
        int m = m0 + tm + i;
        int b = m >> 6;
#pragma unroll
        for (int j = 0; j < 8; j++) {
            int n = n0 + tn + j;
            out[(size_t)m * E_ + n] = (acc[i][j] + bo[n]) * mask[b * E_ + n];
        }
    }
}

// ---------------------------------------------------------------------------
extern "C" void kernel_launch(void* const* d_in, const int* in_sizes, int n_in,
                              void* d_out, int out_size)
{
    const float* x    = (const float*)d_in[0];
    const float* mask = (const float*)d_in[1];
    const float* Wq   = (const float*)d_in[2];
    const float* Wk   = (const float*)d_in[3];
    const float* Wv   = (const float*)d_in[4];
    const float* Wo   = (const float*)d_in[5];
    const float* bo   = (const float*)d_in[6];
    float* out = (float*)d_out;

    float *qp, *kp, *vp, *yp;
    cudaGetSymbolAddress((void**)&qp, g_q);
    cudaGetSymbolAddress((void**)&kp, g_k);
    cudaGetSymbolAddress((void**)&vp, g_v);
    cudaGetSymbolAddress((void**)&yp, g_y);

    const float scale = 0.03125f;   // E^-0.5 = 1/32

    dim3 gqkv(HE_ / 128, M_ / 128); // (64, 16)
    gemm_qkv_kernel<<<gqkv, 256>>>(x, Wq, mask, qp, scale);
    gemm_qkv_kernel<<<gqkv, 256>>>(x, Wk, mask, kp, 1.0f);
    gemm_qkv_kernel<<<gqkv, 256>>>(x, Wv, mask, vp, 1.0f);

    attn_kernel<<<dim3(H_, B_), 256>>>(qp, kp, vp, yp);

    dim3 gout(E_ / 128, M_ / 128);  // (8, 16)
    gemm_out_kernel<<<gout, 256>>>(yp, Wo, bo, mask, out);
}

// round 3
// speedup vs baseline: 5.1286x; 5.1286x over previous
#include <cuda_runtime.h>
#include <cstdint>

#define B_ 32
#define S_ 64
#define H_ 8
#define E_ 1024
#define HE_ 8192
#define M_ 2048

// ---------------- scratch (__device__ globals; no allocs allowed) ----------
__device__ float g_q[B_ * H_ * S_ * E_];
__device__ float g_k[B_ * H_ * S_ * E_];
__device__ float g_v[B_ * H_ * S_ * E_];
__device__ float g_y[M_ * HE_];
__device__ float g_p[B_ * H_ * S_ * S_];
__device__ float g_xt[M_ * E_];
__device__ float g_wq[HE_ * E_];
__device__ float g_wk[HE_ * E_];
__device__ float g_wv[HE_ * E_];
__device__ float g_wo[E_ * HE_];

// ---------------- helpers ---------------------------------------------------
__device__ __forceinline__ float tf32r(float x) {
    uint32_t u;
    asm("cvt.rna.tf32.f32 %0, %1;" : "=r"(u) : "f"(x));
    return __uint_as_float(u);
}

__device__ __forceinline__ void cpasync16(uint32_t dst, const void* src) {
    asm volatile("cp.async.cg.shared.global [%0], [%1], 16;" :: "r"(dst), "l"(src));
}

__device__ __forceinline__ uint32_t s2u(const void* p) {
    uint32_t a;
    asm("{ .reg .u64 t; cvta.to.shared.u64 t, %1; cvt.u32.u64 %0, t; }"
        : "=r"(a) : "l"(p));
    return a;
}

__device__ __forceinline__ void mma_16n8k8(float* d, const uint32_t* a,
                                           const uint32_t* b) {
    asm volatile(
        "mma.sync.aligned.m16n8k8.row.col.f32.tf32.tf32.f32 "
        "{%0,%1,%2,%3}, {%4,%5,%6,%7}, {%8,%9}, {%0,%1,%2,%3};"
        : "+f"(d[0]), "+f"(d[1]), "+f"(d[2]), "+f"(d[3])
        : "r"(a[0]), "r"(a[1]), "r"(a[2]), "r"(a[3]), "r"(b[0]), "r"(b[1]));
}

// ---------------- tf32 rounding pre-pass ------------------------------------
__global__ void __launch_bounds__(256) cvt_tf32_kernel(
    const float4* __restrict__ in, float4* __restrict__ out, int n4)
{
    int i = blockIdx.x * blockDim.x + threadIdx.x;
    if (i < n4) {
        float4 v = in[i];
        v.x = tf32r(v.x); v.y = tf32r(v.y); v.z = tf32r(v.z); v.w = tf32r(v.w);
        out[i] = v;
    }
}

// ---------------- tf32 tensor-core GEMM (mma.sync, NT) ----------------------
// C(M_, Ntot) = A(M_, KTOT) @ W(Ntot, KTOT)^T. Both K-contiguous.
// Block 128x128x32, 256 threads = 8 warps (2 Mgroups x 4 Ngroups),
// warp tile 64x32, mma m16n8k8 tf32. 3-stage cp.async pipeline.
// MODE 0: out[((b*H+h)*S+s)*E+e] = acc * mask[b,e] * scale   (n = h*E+e)
// MODE 1: out[m*E+n] = (acc + bias[n]) * mask[b,n]
#define PAD 36              // floats per smem row (bank-conflict-free)
#define STG (128 * PAD)     // floats per A (or B) stage

template<int KTOT, int MODE>
__global__ void __launch_bounds__(256) gemm_tc(
    const float* __restrict__ A, const float* __restrict__ Wt,
    const float* __restrict__ mask, const float* __restrict__ bias,
    float* __restrict__ out, float scale)
{
    constexpr int NIT = KTOT / 32;
    extern __shared__ float sm[];
    float* smA = sm;                 // 3 stages of A
    float* smB = sm + 3 * STG;       // 3 stages of B

    const int tid = threadIdx.x;
    const int wid = tid >> 5, lane = tid & 31;
    const int wm = wid & 1;          // 0..1  (64-row group)
    const int wn = wid >> 1;         // 0..3  (32-col group)
    const int lr = lane >> 2;        // 0..7
    const int lc = lane & 3;         // 0..3
    const int m0 = blockIdx.y * 128;
    const int n0 = blockIdx.x * 128;

    const int ldrow = tid >> 3;      // 0..31
    const int ldquad = tid & 7;      // 0..7
    const float* Abase = A + (size_t)(m0 + ldrow) * KTOT + ldquad * 4;
    const float* Bbase = Wt + (size_t)(n0 + ldrow) * KTOT + ldquad * 4;
    const uint32_t sAu = s2u(smA);
    const uint32_t sBu = s2u(smB);

    auto load_stage = [&](int s, int kt) {
        const uint32_t dA = sAu + (uint32_t)(s * STG) * 4;
        const uint32_t dB = sBu + (uint32_t)(s * STG) * 4;
        const float* Ap = Abase + kt * 32;
        const float* Bp = Bbase + kt * 32;
#pragma unroll
        for (int p = 0; p < 4; p++) {
            uint32_t doff = (uint32_t)((ldrow + p * 32) * PAD + ldquad * 4) * 4;
            cpasync16(dA + doff, Ap + (size_t)(p * 32) * KTOT);
            cpasync16(dB + doff, Bp + (size_t)(p * 32) * KTOT);
        }
        asm volatile("cp.async.commit_group;" ::: "memory");
    };

    load_stage(0, 0);
    load_stage(1, 1);
    load_stage(2, 2);

    float acc[4][4][4];              // [mt][nt][frag]
#pragma unroll
    for (int i = 0; i < 4; i++)
#pragma unroll
        for (int j = 0; j < 4; j++)
#pragma unroll
            for (int f = 0; f < 4; f++) acc[i][j][f] = 0.0f;

    for (int j = 0; j < NIT; j++) {
        const int s = j % 3;
        asm volatile("cp.async.wait_group 2;" ::: "memory");
        __syncthreads();

        const float* As = smA + s * STG + (wm * 64 + lr) * PAD + lc;
        const float* Bs = smB + s * STG + (wn * 32 + lr) * PAD + lc;

#pragma unroll
        for (int ks = 0; ks < 4; ks++) {
            uint32_t bf[4][2];
#pragma unroll
            for (int nt = 0; nt < 4; nt++) {
                const float* bp = Bs + nt * 8 * PAD + ks * 8;
                bf[nt][0] = __float_as_uint(bp[0]);
                bf[nt][1] = __float_as_uint(bp[4]);
            }
#pragma unroll
            for (int mt = 0; mt < 4; mt++) {
                const float* ap = As + mt * 16 * PAD + ks * 8;
                uint32_t af[4];
                af[0] = __float_as_uint(ap[0]);
                af[1] = __float_as_uint(ap[8 * PAD]);
                af[2] = __float_as_uint(ap[4]);
                af[3] = __float_as_uint(ap[8 * PAD + 4]);
#pragma unroll
                for (int nt = 0; nt < 4; nt++)
                    mma_16n8k8(acc[mt][nt], af, bf[nt]);
            }
        }

        __syncthreads();
        if (j + 3 < NIT) load_stage(s, j + 3);
    }

    // ---- epilogue ----
#pragma unroll
    for (int mt = 0; mt < 4; mt++) {
#pragma unroll
        for (int half = 0; half < 2; half++) {
            const int m = m0 + wm * 64 + mt * 16 + half * 8 + lr;
            const int b = m >> 6;
#pragma unroll
            for (int nt = 0; nt < 4; nt++) {
                const int n = n0 + wn * 32 + nt * 8 + lc * 2;
                float v0 = acc[mt][nt][half * 2 + 0];
                float v1 = acc[mt][nt][half * 2 + 1];
                if (MODE == 0) {
                    const int h = n >> 10;
                    const int e = n & 1023;
                    const int sidx = m & 63;
                    const float* mp = mask + (size_t)b * E_ + e;
                    float2 o;
                    o.x = v0 * mp[0] * scale;
                    o.y = v1 * mp[1] * scale;
                    *(float2*)(out + ((size_t)((b * H_ + h) * S_ + sidx)) * E_ + e) = o;
                } else {
                    const float* mp = mask + (size_t)b * E_ + n;
                    const float* bp = bias + n;
                    float2 o;
                    o.x = (v0 + bp[0]) * mp[0];
                    o.y = (v1 + bp[1]) * mp[1];
                    *(float2*)(out + (size_t)m * E_ + n) = o;
                }
            }
        }
    }
}

// ---------------- attention: logits + softmax -> probs ----------------------
__global__ void __launch_bounds__(256) attn_logits_kernel(
    const float* __restrict__ q, const float* __restrict__ k,
    float* __restrict__ p)
{
    int h = blockIdx.x;
    int b = blockIdx.y;
    const float* qb = q + (size_t)((b * H_ + h) * S_) * E_;
    const float* kb = k + (size_t)((b * H_ + h) * S_) * E_;
    float* pp = p + (size_t)(b * H_ + h) * (S_ * S_);

    __shared__ __align__(16) float sQK[2 * 32 * 68];
    __shared__ __align__(16) float sL[64][68];

    int tid = threadIdx.x;
    int ty = tid >> 4, tx = tid & 15;
    int r0 = ty * 4, c0 = tx * 4;
    float* sQ = sQK;
    float* sK = sQK + 32 * 68;

    float acc[4][4];
#pragma unroll
    for (int i = 0; i < 4; i++)
#pragma unroll
        for (int j = 0; j < 4; j++) acc[i][j] = 0.0f;

    for (int kc = 0; kc < E_; kc += 32) {
#pragma unroll
        for (int l = 0; l < 2; l++) {
            int id = tid * 2 + l;
            int r = id >> 3;
            int cc = (id & 7) * 4;
            float4 qv = *(const float4*)&qb[(size_t)r * E_ + kc + cc];
            sQ[(cc + 0) * 68 + r] = qv.x; sQ[(cc + 1) * 68 + r] = qv.y;
            sQ[(cc + 2) * 68 + r] = qv.z; sQ[(cc + 3) * 68 + r] = qv.w;
            float4 kv = *(const float4*)&kb[(size_t)r * E_ + kc + cc];
            sK[(cc + 0) * 68 + r] = kv.x; sK[(cc + 1) * 68 + r] = kv.y;
            sK[(cc + 2) * 68 + r] = kv.z; sK[(cc + 3) * 68 + r] = kv.w;
        }
        __syncthreads();
#pragma unroll
        for (int kk = 0; kk < 32; kk++) {
            float4 av = *(const float4*)&sQ[kk * 68 + r0];
            float4 bv = *(const float4*)&sK[kk * 68 + c0];
            float a[4] = {av.x, av.y, av.z, av.w};
            float bb[4] = {bv.x, bv.y, bv.z, bv.w};
#pragma unroll
            for (int i = 0; i < 4; i++)
#pragma unroll
                for (int j = 0; j < 4; j++)
                    acc[i][j] = fmaf(a[i], bb[j], acc[i][j]);
        }
        __syncthreads();
    }

#pragma unroll
    for (int i = 0; i < 4; i++)
#pragma unroll
        for (int j = 0; j < 4; j++)
            sL[r0 + i][c0 + j] = acc[i][j];
    __syncthreads();

    {
        int row = tid >> 2;
        int q4 = tid & 3;
        int cb = q4 * 16;
        float mx = -1e30f;
#pragma unroll
        for (int c = 0; c < 16; c++) mx = fmaxf(mx, sL[row][cb + c]);
        mx = fmaxf(mx, __shfl_xor_sync(0xffffffffu, mx, 1));
        mx = fmaxf(mx, __shfl_xor_sync(0xffffffffu, mx, 2));
        float sum = 0.0f;
#pragma unroll
        for (int c = 0; c < 16; c++) {
            float ev = __expf(sL[row][cb + c] - mx);
            sL[row][cb + c] = ev;
            sum += ev;
        }
        sum += __shfl_xor_sync(0xffffffffu, sum, 1);
        sum += __shfl_xor_sync(0xffffffffu, sum, 2);
        float inv = 1.0f / sum;
#pragma unroll
        for (int c = 0; c < 16; c++) sL[row][cb + c] *= inv;
    }
    __syncthreads();

#pragma unroll
    for (int l = 0; l < 4; l++) {
        int id = l * 256 + tid;
        int r = id >> 4;
        int c = (id & 15) * 4;
        float4 t = make_float4(sL[r][c], sL[r][c + 1], sL[r][c + 2], sL[r][c + 3]);
        *(float4*)(pp + r * 64 + c) = t;
    }
}

// ---------------- attention: y = P @ V (per 64-wide e-chunk) -----------------
__global__ void __launch_bounds__(128) attn_av_kernel(
    const float* __restrict__ p, const float* __restrict__ v,
    float* __restrict__ y)
{
    int ec = blockIdx.x & 15;
    int h = blockIdx.x >> 4;
    int b = blockIdx.y;
    const float* pb = p + (size_t)(b * H_ + h) * (S_ * S_);
    const float* vb = v + (size_t)((b * H_ + h) * S_) * E_ + ec * 64;
    float* yb = y + (size_t)b * S_ * HE_ + h * E_ + ec * 64;

    __shared__ float sP[64][66];
    __shared__ float sV[64][68];

    int tid = threadIdx.x;
#pragma unroll
    for (int l = 0; l < 8; l++) {
        int id = l * 128 + tid;
        int r = id >> 4;
        int c = (id & 15) * 4;
        float4 t = *(const float4*)(pb + r * 64 + c);
        sP[r][c] = t.x; sP[r][c + 1] = t.y; sP[r][c + 2] = t.z; sP[r][c + 3] = t.w;
        float4 u = *(const float4*)(vb + (size_t)r * E_ + c);
        sV[r][c] = u.x; sV[r][c + 1] = u.y; sV[r][c + 2] = u.z; sV[r][c + 3] = u.w;
    }
    __syncthreads();

    int ty = tid >> 3;
    int tx = tid & 7;
    int r0 = ty * 4, c0 = tx * 8;

    float acc[4][8];
#pragma unroll
    for (int i = 0; i < 4; i++)
#pragma unroll
        for (int j = 0; j < 8; j++) acc[i][j] = 0.0f;

#pragma unroll 4
    for (int m = 0; m < 64; m++) {
        float vv[8];
        float4 v0 = *(const float4*)&sV[m][c0];
        float4 v1 = *(const float4*)&sV[m][c0 + 4];
        vv[0]=v0.x; vv[1]=v0.y; vv[2]=v0.z; vv[3]=v0.w;
        vv[4]=v1.x; vv[5]=v1.y; vv[6]=v1.z; vv[7]=v1.w;
        float a0 = sP[r0 + 0][m], a1 = sP[r0 + 1][m];
        float a2 = sP[r0 + 2][m], a3 = sP[r0 + 3][m];
#pragma unroll
        for (int j = 0; j < 8; j++) {
            acc[0][j] = fmaf(a0, vv[j], acc[0][j]);
            acc[1][j] = fmaf(a1, vv[j], acc[1][j]);
            acc[2][j] = fmaf(a2, vv[j], acc[2][j]);
            acc[3][j] = fmaf(a3, vv[j], acc[3][j]);
        }
    }

#pragma unroll
    for (int i = 0; i < 4; i++) {
        float* op = yb + (size_t)(r0 + i) * HE_ + c0;
        float4 o0 = make_float4(tf32r(acc[i][0]), tf32r(acc[i][1]),
                                tf32r(acc[i][2]), tf32r(acc[i][3]));
        float4 o1 = make_float4(tf32r(acc[i][4]), tf32r(acc[i][5]),
                                tf32r(acc[i][6]), tf32r(acc[i][7]));
        *(float4*)(op) = o0;
        *(float4*)(op + 4) = o1;
    }
}

// ---------------------------------------------------------------------------
extern "C" void kernel_launch(void* const* d_in, const int* in_sizes, int n_in,
                              void* d_out, int out_size)
{
    const float* x    = (const float*)d_in[0];
    const float* mask = (const float*)d_in[1];
    const float* Wq   = (const float*)d_in[2];
    const float* Wk   = (const float*)d_in[3];
    const float* Wv   = (const float*)d_in[4];
    const float* Wo   = (const float*)d_in[5];
    const float* bo   = (const float*)d_in[6];
    float* out = (float*)d_out;

    float *qp, *kp, *vp, *yp, *pp, *xt, *wq, *wk, *wv, *wo;
    cudaGetSymbolAddress((void**)&qp, g_q);
    cudaGetSymbolAddress((void**)&kp, g_k);
    cudaGetSymbolAddress((void**)&vp, g_v);
    cudaGetSymbolAddress((void**)&yp, g_y);
    cudaGetSymbolAddress((void**)&pp, g_p);
    cudaGetSymbolAddress((void**)&xt, g_xt);
    cudaGetSymbolAddress((void**)&wq, g_wq);
    cudaGetSymbolAddress((void**)&wk, g_wk);
    cudaGetSymbolAddress((void**)&wv, g_wv);
    cudaGetSymbolAddress((void**)&wo, g_wo);

    const int SMEM = 6 * STG * 4;   // 3 stages x (A+B) x 18432B = 110592
    static bool attr_set = false;
    if (!attr_set) {
        cudaFuncSetAttribute(gemm_tc<E_, 0>,
                             cudaFuncAttributeMaxDynamicSharedMemorySize, SMEM);
        cudaFuncSetAttribute(gemm_tc<HE_, 1>,
                             cudaFuncAttributeMaxDynamicSharedMemorySize, SMEM);
        attr_set = true;
    }

    {
        int n4x = (M_ * E_) / 4;
        cvt_tf32_kernel<<<(n4x + 255) / 256, 256>>>((const float4*)x, (float4*)xt, n4x);
        int n4w = (HE_ * E_) / 4;
        cvt_tf32_kernel<<<(n4w + 255) / 256, 256>>>((const float4*)Wq, (float4*)wq, n4w);
        cvt_tf32_kernel<<<(n4w + 255) / 256, 256>>>((const float4*)Wk, (float4*)wk, n4w);
        cvt_tf32_kernel<<<(n4w + 255) / 256, 256>>>((const float4*)Wv, (float4*)wv, n4w);
        cvt_tf32_kernel<<<(n4w + 255) / 256, 256>>>((const float4*)Wo, (float4*)wo, n4w);
    }

    const float scale = 0.03125f;   // E^-0.5

    dim3 g1(HE_ / 128, M_ / 128);   // (64, 16)
    gemm_tc<E_, 0><<<g1, 256, SMEM>>>(xt, wq, mask, nullptr, qp, scale);
    gemm_tc<E_, 0><<<g1, 256, SMEM>>>(xt, wk, mask, nullptr, kp, 1.0f);
    gemm_tc<E_, 0><<<g1, 256, SMEM>>>(xt, wv, mask, nullptr, vp, 1.0f);

    attn_logits_kernel<<<dim3(H_, B_), 256>>>(qp, kp, pp);
    attn_av_kernel<<<dim3(16 * H_, B_), 128>>>(pp, vp, yp);

    dim3 g2(E_ / 128, M_ / 128);    // (8, 16)
    gemm_tc<HE_, 1><<<g2, 256, SMEM>>>(yp, wo, mask, bo, out, 1.0f);
}

// round 4
// speedup vs baseline: 8.5346x; 1.6641x over previous
#include <cuda_runtime.h>
#include <cuda_fp16.h>
#include <cstdint>

#define B_ 32
#define S_ 64
#define H_ 8
#define E_ 1024
#define HE_ 8192
#define M_ 2048

// ---------------- scratch (__device__ globals) ------------------------------
__device__ float  g_q[B_ * H_ * S_ * E_];
__device__ float  g_k[B_ * H_ * S_ * E_];
__device__ float  g_v[B_ * H_ * S_ * E_];
__device__ float  g_p[B_ * H_ * S_ * S_];
__device__ __half g_y[M_ * HE_];
__device__ __half g_xh[M_ * E_];
__device__ __half g_wqkv[3 * HE_ * E_];
__device__ __half g_woh[E_ * HE_];

// ---------------- helpers ---------------------------------------------------
__device__ __forceinline__ uint32_t s2u(const void* p) {
    uint32_t a;
    asm("{ .reg .u64 t; cvta.to.shared.u64 t, %1; cvt.u32.u64 %0, t; }"
        : "=r"(a) : "l"(p));
    return a;
}

__device__ __forceinline__ void cpasync16(uint32_t dst, const void* src) {
    asm volatile("cp.async.cg.shared.global [%0], [%1], 16;" :: "r"(dst), "l"(src));
}

__device__ __forceinline__ uint32_t packh2(float a, float b) {
    __half2 h = __floats2half2_rn(make_float2(a, b).x, make_float2(a, b).y);
    return *reinterpret_cast<uint32_t*>(&h);
}

__device__ __forceinline__ void ldmx4(uint32_t* r, uint32_t addr) {
    asm volatile("ldmatrix.sync.aligned.m8n8.x4.shared.b16 {%0,%1,%2,%3}, [%4];"
                 : "=r"(r[0]), "=r"(r[1]), "=r"(r[2]), "=r"(r[3]) : "r"(addr));
}

__device__ __forceinline__ void mma_f16(float* d, const uint32_t* a,
                                        const uint32_t* b) {
    asm volatile(
        "mma.sync.aligned.m16n8k16.row.col.f32.f16.f16.f32 "
        "{%0,%1,%2,%3}, {%4,%5,%6,%7}, {%8,%9}, {%0,%1,%2,%3};"
        : "+f"(d[0]), "+f"(d[1]), "+f"(d[2]), "+f"(d[3])
        : "r"(a[0]), "r"(a[1]), "r"(a[2]), "r"(a[3]), "r"(b[0]), "r"(b[1]));
}

// ---------------- fp32 -> fp16 conversion pre-pass --------------------------
__global__ void __launch_bounds__(256) cvt_f16_kernel(
    const float4* __restrict__ in, uint2* __restrict__ out, int n4)
{
    int i = blockIdx.x * blockDim.x + threadIdx.x;
    if (i < n4) {
        float4 v = in[i];
        uint2 o;
        o.x = packh2(v.x, v.y);
        o.y = packh2(v.z, v.w);
        out[i] = o;
    }
}

// ---------------- fp16 tensor-core GEMM (NT) --------------------------------
// C(M_, Ntot) = A(M_, KTOT) @ W(Ntot, KTOT)^T, fp16 in, fp32 accum.
// Block 128x128x32, 256 thr = 8 warps (2M x 4N), warp tile 64x32.
// smem: 64B rows (32 halves), 16B-chunk XOR swizzle: chunk' = chunk ^ ((row>>1)&3).
// 3-stage cp.async pipeline.
// MODE 0 (fused QKV): n0 selects {q,k,v} and head; out fp32 * mask * scale.
// MODE 1: out[m*E+n] = (acc + bias[n]) * mask[b,n], fp32.
#define TSTG 8192   // bytes per 128x32-half tile stage

template<int KTOT, int MODE>
__global__ void __launch_bounds__(256) gemm_f16(
    const __half* __restrict__ A, const __half* __restrict__ Wt,
    const float* __restrict__ mask, const float* __restrict__ bias,
    float* __restrict__ o0, float* __restrict__ o1, float* __restrict__ o2)
{
    constexpr int NIT = KTOT / 32;
    extern __shared__ __align__(16) char sm[];
    const uint32_t sAu = s2u(sm);
    const uint32_t sBu = sAu + 3 * TSTG;

    const int tid = threadIdx.x;
    const int wid = tid >> 5, lane = tid & 31;
    const int wm = wid & 1;          // 0..1 (64-row group)
    const int wn = wid >> 1;         // 0..3 (32-col group)
    const int lr = lane >> 2;        // 0..7
    const int lc = lane & 3;         // 0..3
    const int m0 = blockIdx.y * 128;
    const int n0 = blockIdx.x * 128;

    // loader mapping: 2 passes x (row=tid>>2 (+64), chunk=tid&3)
    const int ldrow = tid >> 2;      // 0..63
    const int ldch = tid & 3;
    const __half* Abase = A + (size_t)(m0 + ldrow) * KTOT + ldch * 8;
    const __half* Bbase = Wt + (size_t)(n0 + ldrow) * KTOT + ldch * 8;

    auto load_stage = [&](int s, int kt) {
#pragma unroll
        for (int p = 0; p < 2; p++) {
            int r = ldrow + p * 64;
            uint32_t doff = (uint32_t)(r * 64 + ((ldch ^ ((r >> 1) & 3)) << 4));
            cpasync16(sAu + s * TSTG + doff,
                      Abase + (size_t)p * 64 * KTOT + kt * 32);
            cpasync16(sBu + s * TSTG + doff,
                      Bbase + (size_t)p * 64 * KTOT + kt * 32);
        }
        asm volatile("cp.async.commit_group;" ::: "memory");
    };

    load_stage(0, 0);
    load_stage(1, 1);
    load_stage(2, 2);

    float acc[4][4][4];
#pragma unroll
    for (int i = 0; i < 4; i++)
#pragma unroll
        for (int j = 0; j < 4; j++)
#pragma unroll
            for (int f = 0; f < 4; f++) acc[i][j][f] = 0.0f;

    // fragment lane addressing (row & chunk pieces)
    const int arow0 = wm * 64 + (lane & 15);       // + mt*16
    const int acs = lane >> 4;                     // chunk half-select (0/1)
    const int midx = lane >> 3;
    const int brow0 = wn * 32 + ((midx >> 1) << 3) + (lane & 7);  // + ntp*16
    const int bcs = midx & 1;

    for (int j = 0; j < NIT; j++) {
        const int s = j % 3;
        asm volatile("cp.async.wait_group 2;" ::: "memory");
        __syncthreads();
        const uint32_t As = sAu + s * TSTG;
        const uint32_t Bs = sBu + s * TSTG;

#pragma unroll
        for (int ks = 0; ks < 2; ks++) {
            uint32_t bf[2][4];
#pragma unroll
            for (int ntp = 0; ntp < 2; ntp++) {
                int r = brow0 + ntp * 16;
                int ch = (ks * 2 + bcs) ^ ((r >> 1) & 3);
                ldmx4(bf[ntp], Bs + (uint32_t)(r * 64 + (ch << 4)));
            }
#pragma unroll
            for (int mt = 0; mt < 4; mt++) {
                int r = arow0 + mt * 16;
                int ch = (ks * 2 + acs) ^ ((r >> 1) & 3);
                uint32_t af[4];
                ldmx4(af, As + (uint32_t)(r * 64 + (ch << 4)));
#pragma unroll
                for (int nt = 0; nt < 4; nt++)
                    mma_f16(acc[mt][nt], af, bf[nt >> 1] + (nt & 1) * 2);
            }
        }

        __syncthreads();
        if (j + 3 < NIT) load_stage(s, j + 3);
    }

    // ---- epilogue ----
    // MODE 0: which/head uniform per block (n0 is a multiple of 128)
    float* outsel;
    float scale = 1.0f;
    int h = 0, e0 = 0;
    if (MODE == 0) {
        int which = n0 >> 13;
        outsel = (which == 0) ? o0 : (which == 1) ? o1 : o2;
        if (which == 0) scale = 0.03125f;   // E^-0.5
        h = (n0 >> 10) & 7;
        e0 = n0 & 1023;
    }

#pragma unroll
    for (int mt = 0; mt < 4; mt++) {
#pragma unroll
        for (int half = 0; half < 2; half++) {
            const int m = m0 + wm * 64 + mt * 16 + half * 8 + lr;
            const int b = m >> 6;
#pragma unroll
            for (int nt = 0; nt < 4; nt++) {
                const int nrel = wn * 32 + nt * 8 + lc * 2;
                float v0 = acc[mt][nt][half * 2 + 0];
                float v1 = acc[mt][nt][half * 2 + 1];
                if (MODE == 0) {
                    const int e = e0 + nrel;
                    const int sidx = m & 63;
                    const float* mp = mask + (size_t)b * E_ + e;
                    float2 o;
                    o.x = v0 * mp[0] * scale;
                    o.y = v1 * mp[1] * scale;
                    *(float2*)(outsel +
                        ((size_t)((b * H_ + h) * S_ + sidx)) * E_ + e) = o;
                } else {
                    const int n = n0 + nrel;
                    const float* mp = mask + (size_t)b * E_ + n;
                    float2 o;
                    o.x = (v0 + bias[n]) * mp[0];
                    o.y = (v1 + bias[n + 1]) * mp[1];
                    *(float2*)(o0 + (size_t)m * E_ + n) = o;
                }
            }
        }
    }
}

// ---------------- attention: logits + softmax -> probs ----------------------
__global__ void __launch_bounds__(256) attn_logits_kernel(
    const float* __restrict__ q, const float* __restrict__ k,
    float* __restrict__ p)
{
    int h = blockIdx.x;
    int b = blockIdx.y;
    const float* qb = q + (size_t)((b * H_ + h) * S_) * E_;
    const float* kb = k + (size_t)((b * H_ + h) * S_) * E_;
    float* pp = p + (size_t)(b * H_ + h) * (S_ * S_);

    __shared__ __align__(16) float sQK[2 * 32 * 68];
    __shared__ __align__(16) float sL[64][68];

    int tid = threadIdx.x;
    int ty = tid >> 4, tx = tid & 15;
    int r0 = ty * 4, c0 = tx * 4;
    float* sQ = sQK;
    float* sK = sQK + 32 * 68;

    float acc[4][4];
#pragma unroll
    for (int i = 0; i < 4; i++)
#pragma unroll
        for (int j = 0; j < 4; j++) acc[i][j] = 0.0f;

    for (int kc = 0; kc < E_; kc += 32) {
#pragma unroll
        for (int l = 0; l < 2; l++) {
            int id = tid * 2 + l;
            int r = id >> 3;
            int cc = (id & 7) * 4;
            float4 qv = *(const float4*)&qb[(size_t)r * E_ + kc + cc];
            sQ[(cc + 0) * 68 + r] = qv.x; sQ[(cc + 1) * 68 + r] = qv.y;
            sQ[(cc + 2) * 68 + r] = qv.z; sQ[(cc + 3) * 68 + r] = qv.w;
            float4 kv = *(const float4*)&kb[(size_t)r * E_ + kc + cc];
            sK[(cc + 0) * 68 + r] = kv.x; sK[(cc + 1) * 68 + r] = kv.y;
            sK[(cc + 2) * 68 + r] = kv.z; sK[(cc + 3) * 68 + r] = kv.w;
        }
        __syncthreads();
#pragma unroll
        for (int kk = 0; kk < 32; kk++) {
            float4 av = *(const float4*)&sQ[kk * 68 + r0];
            float4 bv = *(const float4*)&sK[kk * 68 + c0];
            float a[4] = {av.x, av.y, av.z, av.w};
            float bb[4] = {bv.x, bv.y, bv.z, bv.w};
#pragma unroll
            for (int i = 0; i < 4; i++)
#pragma unroll
                for (int j = 0; j < 4; j++)
                    acc[i][j] = fmaf(a[i], bb[j], acc[i][j]);
        }
        __syncthreads();
    }

#pragma unroll
    for (int i = 0; i < 4; i++)
#pragma unroll
        for (int j = 0; j < 4; j++)
            sL[r0 + i][c0 + j] = acc[i][j];
    __syncthreads();

    {
        int row = tid >> 2;
        int q4 = tid & 3;
        int cb = q4 * 16;
        float mx = -1e30f;
#pragma unroll
        for (int c = 0; c < 16; c++) mx = fmaxf(mx, sL[row][cb + c]);
        mx = fmaxf(mx, __shfl_xor_sync(0xffffffffu, mx, 1));
        mx = fmaxf(mx, __shfl_xor_sync(0xffffffffu, mx, 2));
        float sum = 0.0f;
#pragma unroll
        for (int c = 0; c < 16; c++) {
            float ev = __expf(sL[row][cb + c] - mx);
            sL[row][cb + c] = ev;
            sum += ev;
        }
        sum += __shfl_xor_sync(0xffffffffu, sum, 1);
        sum += __shfl_xor_sync(0xffffffffu, sum, 2);
        float inv = 1.0f / sum;
#pragma unroll
        for (int c = 0; c < 16; c++) sL[row][cb + c] *= inv;
    }
    __syncthreads();

#pragma unroll
    for (int l = 0; l < 4; l++) {
        int id = l * 256 + tid;
        int r = id >> 4;
        int c = (id & 15) * 4;
        float4 t = make_float4(sL[r][c], sL[r][c + 1], sL[r][c + 2], sL[r][c + 3]);
        *(float4*)(pp + r * 64 + c) = t;
    }
}

// ---------------- attention: y = P @ V (per 64-wide e-chunk), fp16 out -----
__global__ void __launch_bounds__(128) attn_av_kernel(
    const float* __restrict__ p, const float* __restrict__ v,
    __half* __restrict__ y)
{
    int ec = blockIdx.x & 15;
    int h = blockIdx.x >> 4;
    int b = blockIdx.y;
    const float* pb = p + (size_t)(b * H_ + h) * (S_ * S_);
    const float* vb = v + (size_t)((b * H_ + h) * S_) * E_ + ec * 64;
    __half* yb = y + (size_t)b * S_ * HE_ + h * E_ + ec * 64;

    __shared__ float sP[64][66];
    __shared__ float sV[64][68];

    int tid = threadIdx.x;
#pragma unroll
    for (int l = 0; l < 8; l++) {
        int id = l * 128 + tid;
        int r = id >> 4;
        int c = (id & 15) * 4;
        float4 t = *(const float4*)(pb + r * 64 + c);
        sP[r][c] = t.x; sP[r][c + 1] = t.y; sP[r][c + 2] = t.z; sP[r][c + 3] = t.w;
        float4 u = *(const float4*)(vb + (size_t)r * E_ + c);
        sV[r][c] = u.x; sV[r][c + 1] = u.y; sV[r][c + 2] = u.z; sV[r][c + 3] = u.w;
    }
    __syncthreads();

    int ty = tid >> 3;
    int tx = tid & 7;
    int r0 = ty * 4, c0 = tx * 8;

    float acc[4][8];
#pragma unroll
    for (int i = 0; i < 4; i++)
#pragma unroll
        for (int j = 0; j < 8; j++) acc[i][j] = 0.0f;

#pragma unroll 4
    for (int m = 0; m < 64; m++) {
        float vv[8];
        float4 v0 = *(const float4*)&sV[m][c0];
        float4 v1 = *(const float4*)&sV[m][c0 + 4];
        vv[0]=v0.x; vv[1]=v0.y; vv[2]=v0.z; vv[3]=v0.w;
        vv[4]=v1.x; vv[5]=v1.y; vv[6]=v1.z; vv[7]=v1.w;
        float a0 = sP[r0 + 0][m], a1 = sP[r0 + 1][m];
        float a2 = sP[r0 + 2][m], a3 = sP[r0 + 3][m];
#pragma unroll
        for (int j = 0; j < 8; j++) {
            acc[0][j] = fmaf(a0, vv[j], acc[0][j]);
            acc[1][j] = fmaf(a1, vv[j], acc[1][j]);
            acc[2][j] = fmaf(a2, vv[j], acc[2][j]);
            acc[3][j] = fmaf(a3, vv[j], acc[3][j]);
        }
    }

#pragma unroll
    for (int i = 0; i < 4; i++) {
        uint4 o;
        o.x = packh2(acc[i][0], acc[i][1]);
        o.y = packh2(acc[i][2], acc[i][3]);
        o.z = packh2(acc[i][4], acc[i][5]);
        o.w = packh2(acc[i][6], acc[i][7]);
        *(uint4*)(yb + (size_t)(r0 + i) * HE_ + c0) = o;
    }
}

// ---------------------------------------------------------------------------
extern "C" void kernel_launch(void* const* d_in, const int* in_sizes, int n_in,
                              void* d_out, int out_size)
{
    const float* x    = (const float*)d_in[0];
    const float* mask = (const float*)d_in[1];
    const float* Wq   = (const float*)d_in[2];
    const float* Wk   = (const float*)d_in[3];
    const float* Wv   = (const float*)d_in[4];
    const float* Wo   = (const float*)d_in[5];
    const float* bo   = (const float*)d_in[6];
    float* out = (float*)d_out;

    float *qp, *kp, *vp, *pp;
    __half *yh, *xh, *wqkv, *woh;
    cudaGetSymbolAddress((void**)&qp, g_q);
    cudaGetSymbolAddress((void**)&kp, g_k);
    cudaGetSymbolAddress((void**)&vp, g_v);
    cudaGetSymbolAddress((void**)&pp, g_p);
    cudaGetSymbolAddress((void**)&yh, g_y);
    cudaGetSymbolAddress((void**)&xh, g_xh);
    cudaGetSymbolAddress((void**)&wqkv, g_wqkv);
    cudaGetSymbolAddress((void**)&woh, g_woh);

    const int SMEM = 6 * TSTG;   // 49152 B
    static bool attr_set = false;
    if (!attr_set) {
        cudaFuncSetAttribute(gemm_f16<E_, 0>,
                             cudaFuncAttributeMaxDynamicSharedMemorySize, SMEM);
        cudaFuncSetAttribute(gemm_f16<HE_, 1>,
                             cudaFuncAttributeMaxDynamicSharedMemorySize, SMEM);
        attr_set = true;
    }

    // fp32 -> fp16 conversions
    {
        int n4x = (M_ * E_) / 4;
        cvt_f16_kernel<<<(n4x + 255) / 256, 256>>>(
            (const float4*)x, (uint2*)xh, n4x);
        int n4w = (HE_ * E_) / 4;
        cvt_f16_kernel<<<(n4w + 255) / 256, 256>>>(
            (const float4*)Wq, (uint2*)(wqkv), n4w);
        cvt_f16_kernel<<<(n4w + 255) / 256, 256>>>(
            (const float4*)Wk, (uint2*)(wqkv + (size_t)HE_ * E_), n4w);
        cvt_f16_kernel<<<(n4w + 255) / 256, 256>>>(
            (const float4*)Wv, (uint2*)(wqkv + 2 * (size_t)HE_ * E_), n4w);
        cvt_f16_kernel<<<(n4w + 255) / 256, 256>>>(
            (const float4*)Wo, (uint2*)woh, n4w);
    }

    // fused QKV projection: N = 3*HE = 24576
    dim3 g1(3 * HE_ / 128, M_ / 128);   // (192, 16)
    gemm_f16<E_, 0><<<g1, 256, SMEM>>>(xh, wqkv, mask, nullptr, qp, kp, vp);

    attn_logits_kernel<<<dim3(H_, B_), 256>>>(qp, kp, pp);
    attn_av_kernel<<<dim3(16 * H_, B_), 128>>>(pp, vp, yh);

    // output projection
    dim3 g2(E_ / 128, M_ / 128);        // (8, 16)
    gemm_f16<HE_, 1><<<g2, 256, SMEM>>>(yh, woh, mask, bo, out, nullptr, nullptr);
}

// round 5
// speedup vs baseline: 10.7433x; 1.2588x over previous
#include <cuda_runtime.h>
#include <cuda_fp16.h>
#include <cstdint>

#define B_ 32
#define S_ 64
#define H_ 8
#define E_ 1024
#define HE_ 8192
#define M_ 2048

// ---------------- scratch (__device__ globals) ------------------------------
__device__ __half g_qh[B_ * H_ * S_ * E_];
__device__ __half g_kh[B_ * H_ * S_ * E_];
__device__ __half g_vh[B_ * H_ * S_ * E_];
__device__ __half g_y[M_ * HE_];
__device__ __half g_xh[M_ * E_];
__device__ __half g_wqkv[3 * HE_ * E_];
__device__ __half g_woh[E_ * HE_];

// ---------------- helpers ---------------------------------------------------
__device__ __forceinline__ uint32_t s2u(const void* p) {
    uint32_t a;
    asm("{ .reg .u64 t; cvta.to.shared.u64 t, %1; cvt.u32.u64 %0, t; }"
        : "=r"(a) : "l"(p));
    return a;
}

__device__ __forceinline__ void cpasync16(uint32_t dst, const void* src) {
    asm volatile("cp.async.cg.shared.global [%0], [%1], 16;" :: "r"(dst), "l"(src));
}

__device__ __forceinline__ uint32_t packh2(float a, float b) {
    __half2 h = __floats2half2_rn(a, b);
    return *reinterpret_cast<uint32_t*>(&h);
}

__device__ __forceinline__ void ldmx4(uint32_t* r, uint32_t addr) {
    asm volatile("ldmatrix.sync.aligned.m8n8.x4.shared.b16 {%0,%1,%2,%3}, [%4];"
                 : "=r"(r[0]), "=r"(r[1]), "=r"(r[2]), "=r"(r[3]) : "r"(addr));
}

__device__ __forceinline__ void ldmx4t(uint32_t* r, uint32_t addr) {
    asm volatile("ldmatrix.sync.aligned.m8n8.x4.trans.shared.b16 {%0,%1,%2,%3}, [%4];"
                 : "=r"(r[0]), "=r"(r[1]), "=r"(r[2]), "=r"(r[3]) : "r"(addr));
}

__device__ __forceinline__ void mma_f16(float* d, const uint32_t* a,
                                        const uint32_t* b) {
    asm volatile(
        "mma.sync.aligned.m16n8k16.row.col.f32.f16.f16.f32 "
        "{%0,%1,%2,%3}, {%4,%5,%6,%7}, {%8,%9}, {%0,%1,%2,%3};"
        : "+f"(d[0]), "+f"(d[1]), "+f"(d[2]), "+f"(d[3])
        : "r"(a[0]), "r"(a[1]), "r"(a[2]), "r"(a[3]), "r"(b[0]), "r"(b[1]));
}

// ---------------- fused fp32->fp16 conversion (all 5 tensors, 1 launch) -----
#define N4X  (M_ * E_ / 4)        // 524288
#define N4W  (HE_ * E_ / 4)       // 2097152
__global__ void __launch_bounds__(256) cvt_all_kernel(
    const float4* __restrict__ x,
    const float4* __restrict__ wq, const float4* __restrict__ wk,
    const float4* __restrict__ wv, const float4* __restrict__ wo,
    uint2* __restrict__ xh, uint2* __restrict__ wqkvh, uint2* __restrict__ woh)
{
    int i = blockIdx.x * blockDim.x + threadIdx.x;
    const float4* src;
    uint2* dst;
    if (i < N4X)                { src = x + i;               dst = xh + i; }
    else if (i < N4X + N4W)     { int j = i - N4X;           src = wq + j; dst = wqkvh + j; }
    else if (i < N4X + 2 * N4W) { int j = i - N4X - N4W;     src = wk + j; dst = wqkvh + N4W + j; }
    else if (i < N4X + 3 * N4W) { int j = i - N4X - 2 * N4W; src = wv + j; dst = wqkvh + 2 * N4W + j; }
    else if (i < N4X + 4 * N4W) { int j = i - N4X - 3 * N4W; src = wo + j; dst = woh + j; }
    else return;
    float4 v = *src;
    uint2 o;
    o.x = packh2(v.x, v.y);
    o.y = packh2(v.z, v.w);
    *dst = o;
}
#define CVT_TOT (N4X + 4 * N4W)

// ---------------- fp16 tensor-core GEMM (NT) --------------------------------
// Block 128x128x32, 256 thr = 8 warps (2M x 4N), warp tile 64x32.
// smem 64B rows, 16B-chunk XOR swizzle (chunk ^= (row>>1)&3). 3-stage cp.async.
// MODE 0 (fused QKV, fp16 out): n0 -> {q,k,v}+head; val*mask*scale.
// MODE 1 (fp32 out): (acc + bias) * mask.
#define TSTG 8192

template<int KTOT, int MODE>
__global__ void __launch_bounds__(256) gemm_f16(
    const __half* __restrict__ A, const __half* __restrict__ Wt,
    const float* __restrict__ mask, const float* __restrict__ bias,
    void* __restrict__ p0, void* __restrict__ p1, void* __restrict__ p2)
{
    constexpr int NIT = KTOT / 32;
    extern __shared__ __align__(16) char sm[];
    const uint32_t sAu = s2u(sm);
    const uint32_t sBu = sAu + 3 * TSTG;

    const int tid = threadIdx.x;
    const int wid = tid >> 5, lane = tid & 31;
    const int wm = wid & 1;
    const int wn = wid >> 1;
    const int lr = lane >> 2;
    const int lc = lane & 3;
    const int m0 = blockIdx.y * 128;
    const int n0 = blockIdx.x * 128;

    const int ldrow = tid >> 2;
    const int ldch = tid & 3;
    const __half* Abase = A + (size_t)(m0 + ldrow) * KTOT + ldch * 8;
    const __half* Bbase = Wt + (size_t)(n0 + ldrow) * KTOT + ldch * 8;

    auto load_stage = [&](int s, int kt) {
#pragma unroll
        for (int p = 0; p < 2; p++) {
            int r = ldrow + p * 64;
            uint32_t doff = (uint32_t)(r * 64 + ((ldch ^ ((r >> 1) & 3)) << 4));
            cpasync16(sAu + s * TSTG + doff, Abase + (size_t)p * 64 * KTOT + kt * 32);
            cpasync16(sBu + s * TSTG + doff, Bbase + (size_t)p * 64 * KTOT + kt * 32);
        }
        asm volatile("cp.async.commit_group;" ::: "memory");
    };

    load_stage(0, 0);
    load_stage(1, 1);
    load_stage(2, 2);

    float acc[4][4][4];
#pragma unroll
    for (int i = 0; i < 4; i++)
#pragma unroll
        for (int j = 0; j < 4; j++)
#pragma unroll
            for (int f = 0; f < 4; f++) acc[i][j][f] = 0.0f;

    const int arow0 = wm * 64 + (lane & 15);
    const int acs = lane >> 4;
    const int midx = lane >> 3;
    const int brow0 = wn * 32 + ((midx >> 1) << 3) + (lane & 7);
    const int bcs = midx & 1;

    for (int j = 0; j < NIT; j++) {
        const int s = j % 3;
        asm volatile("cp.async.wait_group 2;" ::: "memory");
        __syncthreads();
        const uint32_t As = sAu + s * TSTG;
        const uint32_t Bs = sBu + s * TSTG;

#pragma unroll
        for (int ks = 0; ks < 2; ks++) {
            uint32_t bf[2][4];
#pragma unroll
            for (int ntp = 0; ntp < 2; ntp++) {
                int r = brow0 + ntp * 16;
                int ch = (ks * 2 + bcs) ^ ((r >> 1) & 3);
                ldmx4(bf[ntp], Bs + (uint32_t)(r * 64 + (ch << 4)));
            }
#pragma unroll
            for (int mt = 0; mt < 4; mt++) {
                int r = arow0 + mt * 16;
                int ch = (ks * 2 + acs) ^ ((r >> 1) & 3);
                uint32_t af[4];
                ldmx4(af, As + (uint32_t)(r * 64 + (ch << 4)));
#pragma unroll
                for (int nt = 0; nt < 4; nt++)
                    mma_f16(acc[mt][nt], af, bf[nt >> 1] + (nt & 1) * 2);
            }
        }

        __syncthreads();
        if (j + 3 < NIT) load_stage(s, j + 3);
    }

    // ---- epilogue ----
    __half* outh = nullptr;
    float scale = 1.0f;
    int h = 0, e0 = 0;
    if (MODE == 0) {
        int which = n0 >> 13;
        outh = (__half*)((which == 0) ? p0 : (which == 1) ? p1 : p2);
        if (which == 0) scale = 0.03125f;   // E^-0.5
        h = (n0 >> 10) & 7;
        e0 = n0 & 1023;
    }

#pragma unroll
    for (int mt = 0; mt < 4; mt++) {
#pragma unroll
        for (int half = 0; half < 2; half++) {
            const int m = m0 + wm * 64 + mt * 16 + half * 8 + lr;
            const int b = m >> 6;
#pragma unroll
            for (int nt = 0; nt < 4; nt++) {
                const int nrel = wn * 32 + nt * 8 + lc * 2;
                float v0 = acc[mt][nt][half * 2 + 0];
                float v1 = acc[mt][nt][half * 2 + 1];
                if (MODE == 0) {
                    const int e = e0 + nrel;
                    const int sidx = m & 63;
                    const float* mp = mask + (size_t)b * E_ + e;
                    uint32_t o = packh2(v0 * mp[0] * scale, v1 * mp[1] * scale);
                    *(uint32_t*)(outh +
                        ((size_t)((b * H_ + h) * S_ + sidx)) * E_ + e) = o;
                } else {
                    const int n = n0 + nrel;
                    const float* mp = mask + (size_t)b * E_ + n;
                    float2 o;
                    o.x = (v0 + bias[n]) * mp[0];
                    o.y = (v1 + bias[n + 1]) * mp[1];
                    *(float2*)((float*)p0 + (size_t)m * E_ + n) = o;
                }
            }
        }
    }
}

// ---------------- fused attention (one block per (b,h)) ---------------------
// Phase 1: S(64x64) = Q@K^T over E=1024, fp16 mma, fp32 accum.
// Softmax fp32. Phase 2: y = P@V with V^T via ldmatrix.trans, fp16 out.
// smem layout (bytes):
//   sQ0 @ 0, sQ1 @ 9216, sK0 @ 18432, sK1 @ 27648   (64 rows x 144B)
//   sL  @ 36864 (64 x 68 fp32 = 17408)
//   phase2: sP @ 0 (64 x 144B), sV0 @ 9216, sV1 @ 26624 (64 rows x 272B)
#define ATT_SMEM 54272

__global__ void __launch_bounds__(256) attn_fused_kernel(
    const __half* __restrict__ q, const __half* __restrict__ k,
    const __half* __restrict__ v, __half* __restrict__ y)
{
    const int h = blockIdx.x;
    const int b = blockIdx.y;
    const __half* qb = q + (size_t)((b * H_ + h) * S_) * E_;
    const __half* kb = k + (size_t)((b * H_ + h) * S_) * E_;
    const __half* vb = v + (size_t)((b * H_ + h) * S_) * E_;
    __half* yb = y + (size_t)b * S_ * HE_ + h * E_;

    extern __shared__ __align__(16) char sm[];
    const uint32_t sb = s2u(sm);
    const uint32_t sQ[2] = { sb, sb + 9216 };
    const uint32_t sK[2] = { sb + 18432, sb + 27648 };
    float* sL = (float*)(sm + 36864);
    const uint32_t sP = sb;
    const uint32_t sV[2] = { sb + 9216, sb + 26624 };

    const int tid = threadIdx.x;
    const int wid = tid >> 5, lane = tid & 31;
    const int ldr = tid >> 2;       // 0..63
    const int ldc = tid & 3;        // 0..3

    // ---- phase 1: logits ----
    auto loadQK = [&](int s, int kc) {
        const __half* qs = qb + (size_t)ldr * E_ + kc * 64 + ldc * 8;
        const __half* ks = kb + (size_t)ldr * E_ + kc * 64 + ldc * 8;
        uint32_t d = (uint32_t)(ldr * 144 + ldc * 16);
        cpasync16(sQ[s] + d, qs);
        cpasync16(sQ[s] + d + 64, qs + 32);
        cpasync16(sK[s] + d, ks);
        cpasync16(sK[s] + d + 64, ks + 32);
        asm volatile("cp.async.commit_group;" ::: "memory");
    };

    loadQK(0, 0);
    loadQK(1, 1);

    const int wm = wid & 3;         // 16-row group
    const int wn = wid >> 2;        // 32-col group
    const int arow = wm * 16 + (lane & 15);
    const int acs = lane >> 4;
    const int midx = lane >> 3;
    const int brow = wn * 32 + ((midx >> 1) << 3) + (lane & 7);
    const int bcs = midx & 1;

    float acc[4][4];
#pragma unroll
    for (int i = 0; i < 4; i++)
#pragma unroll
        for (int f = 0; f < 4; f++) acc[i][f] = 0.0f;

    for (int c = 0; c < 16; c++) {
        const int cur = c & 1;
        asm volatile("cp.async.wait_group 1;" ::: "memory");
        __syncthreads();
#pragma unroll
        for (int ks = 0; ks < 4; ks++) {
            uint32_t af[4];
            ldmx4(af, sQ[cur] + (uint32_t)(arow * 144 + ks * 32 + acs * 16));
            uint32_t bf[2][4];
#pragma unroll
            for (int ntp = 0; ntp < 2; ntp++)
                ldmx4(bf[ntp], sK[cur] + (uint32_t)((brow + ntp * 16) * 144 +
                                                    ks * 32 + bcs * 16));
#pragma unroll
            for (int nt = 0; nt < 4; nt++)
                mma_f16(acc[nt], af, bf[nt >> 1] + (nt & 1) * 2);
        }
        __syncthreads();
        if (c + 2 < 16) loadQK(cur, c + 2);
        else asm volatile("cp.async.commit_group;" ::: "memory");
    }

    // write logits to sL
    {
        const int r0 = wm * 16 + (lane >> 2);
        const int cbase = wn * 32 + (lane & 3) * 2;
#pragma unroll
        for (int nt = 0; nt < 4; nt++) {
            sL[(r0)     * 68 + cbase + nt * 8]     = acc[nt][0];
            sL[(r0)     * 68 + cbase + nt * 8 + 1] = acc[nt][1];
            sL[(r0 + 8) * 68 + cbase + nt * 8]     = acc[nt][2];
            sL[(r0 + 8) * 68 + cbase + nt * 8 + 1] = acc[nt][3];
        }
    }
    __syncthreads();

    // ---- softmax (4 threads per row) + write P to sP (fp16) ----
    {
        const int row = tid >> 2;
        const int cb = (tid & 3) * 16;
        float mx = -1e30f;
#pragma unroll
        for (int c = 0; c < 16; c++) mx = fmaxf(mx, sL[row * 68 + cb + c]);
        mx = fmaxf(mx, __shfl_xor_sync(0xffffffffu, mx, 1));
        mx = fmaxf(mx, __shfl_xor_sync(0xffffffffu, mx, 2));
        float ev[16];
        float sum = 0.0f;
#pragma unroll
        for (int c = 0; c < 16; c++) {
            ev[c] = __expf(sL[row * 68 + cb + c] - mx);
            sum += ev[c];
        }
        sum += __shfl_xor_sync(0xffffffffu, sum, 1);
        sum += __shfl_xor_sync(0xffffffffu, sum, 2);
        float inv = 1.0f / sum;
        __syncthreads();   // all reads of sL done before sP overwrites sQ0
#pragma unroll
        for (int c = 0; c < 8; c++) {
            uint32_t pk = packh2(ev[c * 2] * inv, ev[c * 2 + 1] * inv);
            *(uint32_t*)(sm + (row * 144 + (cb + c * 2) * 2)) = pk;
        }
    }
    __syncthreads();

    // ---- phase 2: y = P @ V ----
    auto loadV = [&](int s, int ec) {
        const __half* vs = vb + (size_t)ldr * E_ + ec * 128 + ldc * 8;
        uint32_t d = (uint32_t)(ldr * 272 + ldc * 16);
#pragma unroll
        for (int jj = 0; jj < 4; jj++)
            cpasync16(sV[s] + d + jj * 64, vs + jj * 32);
        asm volatile("cp.async.commit_group;" ::: "memory");
    };

    loadV(0, 0);
    loadV(1, 1);

    const int wm2 = wid & 1;        // 32-row group
    const int wn2 = wid >> 1;       // 32-col group (of 128)
    const int prow0 = wm2 * 32 + (lane & 15);
    const int vs0 = ((lane >> 3) & 1) * 8 + (lane & 7);
    const int ve0 = wn2 * 32 + (lane >> 4) * 8;

    for (int ec = 0; ec < 8; ec++) {
        const int cur = ec & 1;
        asm volatile("cp.async.wait_group 1;" ::: "memory");
        __syncthreads();

        float acc2[2][4][4];
#pragma unroll
        for (int i = 0; i < 2; i++)
#pragma unroll
            for (int j = 0; j < 4; j++)
#pragma unroll
                for (int f = 0; f < 4; f++) acc2[i][j][f] = 0.0f;

#pragma unroll
        for (int ks = 0; ks < 4; ks++) {
            uint32_t bf[2][4];
#pragma unroll
            for (int ntp = 0; ntp < 2; ntp++)
                ldmx4t(bf[ntp], sV[cur] + (uint32_t)((ks * 16 + vs0) * 272 +
                                                     (ve0 + ntp * 16) * 2));
#pragma unroll
            for (int mt = 0; mt < 2; mt++) {
                uint32_t af[4];
                ldmx4(af, sP + (uint32_t)((prow0 + mt * 16) * 144 +
                                          ks * 32 + acs * 16));
#pragma unroll
                for (int nt = 0; nt < 4; nt++)
                    mma_f16(acc2[mt][nt], af, bf[nt >> 1] + (nt & 1) * 2);
            }
        }

        // store this e-chunk
#pragma unroll
        for (int mt = 0; mt < 2; mt++) {
#pragma unroll
            for (int half = 0; half < 2; half++) {
                const int row = wm2 * 32 + mt * 16 + half * 8 + (lane >> 2);
#pragma unroll
                for (int nt = 0; nt < 4; nt++) {
                    const int col = ec * 128 + wn2 * 32 + nt * 8 + (lane & 3) * 2;
                    uint32_t o = packh2(acc2[mt][nt][half * 2],
                                        acc2[mt][nt][half * 2 + 1]);
                    *(uint32_t*)(yb + (size_t)row * HE_ + col) = o;
                }
            }
        }

        __syncthreads();
        if (ec + 2 < 8) loadV(cur, ec + 2);
        else asm volatile("cp.async.commit_group;" ::: "memory");
    }
}

// ---------------------------------------------------------------------------
extern "C" void kernel_launch(void* const* d_in, const int* in_sizes, int n_in,
                              void* d_out, int out_size)
{
    const float* x    = (const float*)d_in[0];
    const float* mask = (const float*)d_in[1];
    const float* Wq   = (const float*)d_in[2];
    const float* Wk   = (const float*)d_in[3];
    const float* Wv   = (const float*)d_in[4];
    const float* Wo   = (const float*)d_in[5];
    const float* bo   = (const float*)d_in[6];
    float* out = (float*)d_out;

    __half *qh, *kh, *vh, *yh, *xh, *wqkv, *woh;
    cudaGetSymbolAddress((void**)&qh, g_qh);
    cudaGetSymbolAddress((void**)&kh, g_kh);
    cudaGetSymbolAddress((void**)&vh, g_vh);
    cudaGetSymbolAddress((void**)&yh, g_y);
    cudaGetSymbolAddress((void**)&xh, g_xh);
    cudaGetSymbolAddress((void**)&wqkv, g_wqkv);
    cudaGetSymbolAddress((void**)&woh, g_woh);

    const int SMEM = 6 * TSTG;   // 49152
    static bool attr_set = false;
    if (!attr_set) {
        cudaFuncSetAttribute(gemm_f16<E_, 0>,
                             cudaFuncAttributeMaxDynamicSharedMemorySize, SMEM);
        cudaFuncSetAttribute(gemm_f16<HE_, 1>,
                             cudaFuncAttributeMaxDynamicSharedMemorySize, SMEM);
        cudaFuncSetAttribute(attn_fused_kernel,
                             cudaFuncAttributeMaxDynamicSharedMemorySize, ATT_SMEM);
        attr_set = true;
    }

    // one fused conversion launch
    cvt_all_kernel<<<(CVT_TOT + 255) / 256, 256>>>(
        (const float4*)x, (const float4*)Wq, (const float4*)Wk,
        (const float4*)Wv, (const float4*)Wo,
        (uint2*)xh, (uint2*)wqkv, (uint2*)woh);

    // fused QKV projection: N = 3*HE = 24576
    dim3 g1(3 * HE_ / 128, M_ / 128);   // (192, 16)
    gemm_f16<E_, 0><<<g1, 256, SMEM>>>(xh, wqkv, mask, nullptr, qh, kh, vh);

    // fused attention
    attn_fused_kernel<<<dim3(H_, B_), 256, ATT_SMEM>>>(qh, kh, vh, yh);

    // output projection
    dim3 g2(E_ / 128, M_ / 128);        // (8, 16)
    gemm_f16<HE_, 1><<<g2, 256, SMEM>>>(yh, woh, mask, bo, out, nullptr, nullptr);
}

// round 6
// speedup vs baseline: 11.2983x; 1.0517x over previous
#include <cuda_runtime.h>
#include <cuda_fp16.h>
#include <cstdint>

#define B_ 32
#define S_ 64
#define H_ 8
#define E_ 1024
#define HE_ 8192
#define M_ 2048
#define NSPLIT 4
#define KSPL (HE_ / NSPLIT)   // 2048

// ---------------- scratch (__device__ globals) ------------------------------
__device__ __half g_qh[B_ * H_ * S_ * E_];
__device__ __half g_kh[B_ * H_ * S_ * E_];
__device__ __half g_vh[B_ * H_ * S_ * E_];
__device__ __half g_y[M_ * HE_];
__device__ __half g_xh[M_ * E_];
__device__ __half g_wqkv[3 * HE_ * E_];
__device__ __half g_woh[E_ * HE_];
__device__ float  g_part[NSPLIT * M_ * E_];

// ---------------- helpers ---------------------------------------------------
__device__ __forceinline__ uint32_t s2u(const void* p) {
    uint32_t a;
    asm("{ .reg .u64 t; cvta.to.shared.u64 t, %1; cvt.u32.u64 %0, t; }"
        : "=r"(a) : "l"(p));
    return a;
}

__device__ __forceinline__ void cpasync16(uint32_t dst, const void* src) {
    asm volatile("cp.async.cg.shared.global [%0], [%1], 16;" :: "r"(dst), "l"(src));
}

__device__ __forceinline__ uint32_t packh2(float a, float b) {
    __half2 h = __floats2half2_rn(a, b);
    return *reinterpret_cast<uint32_t*>(&h);
}

__device__ __forceinline__ void ldmx4(uint32_t* r, uint32_t addr) {
    asm volatile("ldmatrix.sync.aligned.m8n8.x4.shared.b16 {%0,%1,%2,%3}, [%4];"
                 : "=r"(r[0]), "=r"(r[1]), "=r"(r[2]), "=r"(r[3]) : "r"(addr));
}

__device__ __forceinline__ void ldmx4t(uint32_t* r, uint32_t addr) {
    asm volatile("ldmatrix.sync.aligned.m8n8.x4.trans.shared.b16 {%0,%1,%2,%3}, [%4];"
                 : "=r"(r[0]), "=r"(r[1]), "=r"(r[2]), "=r"(r[3]) : "r"(addr));
}

__device__ __forceinline__ void mma_f16(float* d, const uint32_t* a,
                                        const uint32_t* b) {
    asm volatile(
        "mma.sync.aligned.m16n8k16.row.col.f32.f16.f16.f32 "
        "{%0,%1,%2,%3}, {%4,%5,%6,%7}, {%8,%9}, {%0,%1,%2,%3};"
        : "+f"(d[0]), "+f"(d[1]), "+f"(d[2]), "+f"(d[3])
        : "r"(a[0]), "r"(a[1]), "r"(a[2]), "r"(a[3]), "r"(b[0]), "r"(b[1]));
}

// ---------------- fused fp32->fp16 conversion -------------------------------
#define N4X  (M_ * E_ / 4)
#define N4W  (HE_ * E_ / 4)
__global__ void __launch_bounds__(256) cvt_all_kernel(
    const float4* __restrict__ x,
    const float4* __restrict__ wq, const float4* __restrict__ wk,
    const float4* __restrict__ wv, const float4* __restrict__ wo,
    uint2* __restrict__ xh, uint2* __restrict__ wqkvh, uint2* __restrict__ woh)
{
    int i = blockIdx.x * blockDim.x + threadIdx.x;
    const float4* src;
    uint2* dst;
    if (i < N4X)                { src = x + i;               dst = xh + i; }
    else if (i < N4X + N4W)     { int j = i - N4X;           src = wq + j; dst = wqkvh + j; }
    else if (i < N4X + 2 * N4W) { int j = i - N4X - N4W;     src = wk + j; dst = wqkvh + N4W + j; }
    else if (i < N4X + 3 * N4W) { int j = i - N4X - 2 * N4W; src = wv + j; dst = wqkvh + 2 * N4W + j; }
    else if (i < N4X + 4 * N4W) { int j = i - N4X - 3 * N4W; src = wo + j; dst = woh + j; }
    else return;
    float4 v = *src;
    uint2 o;
    o.x = packh2(v.x, v.y);
    o.y = packh2(v.z, v.w);
    *dst = o;
}
#define CVT_TOT (N4X + 4 * N4W)

// ---------------- fp16 tensor-core GEMM (NT) --------------------------------
// MODE 0 (fused QKV, fp16 out): n0 selects {q,k,v}+head; val*mask*scale.
// MODE 2 (split-K partial): plain fp32 partial into g_part slice blockIdx.z.
#define TSTG 8192

template<int KTOT, int KITER, int MODE>
__global__ void __launch_bounds__(256) gemm_f16(
    const __half* __restrict__ A, const __half* __restrict__ Wt,
    const float* __restrict__ mask,
    void* __restrict__ p0, void* __restrict__ p1, void* __restrict__ p2)
{
    constexpr int NIT = KITER / 32;
    extern __shared__ __align__(16) char sm[];
    const uint32_t sAu = s2u(sm);
    const uint32_t sBu = sAu + 3 * TSTG;

    const int tid = threadIdx.x;
    const int wid = tid >> 5, lane = tid & 31;
    const int wm = wid & 1;
    const int wn = wid >> 1;
    const int lr = lane >> 2;
    const int lc = lane & 3;
    const int m0 = blockIdx.y * 128;
    const int n0 = blockIdx.x * 128;
    const int k0 = (MODE == 2) ? blockIdx.z * KITER : 0;

    const int ldrow = tid >> 2;
    const int ldch = tid & 3;
    const __half* Abase = A + (size_t)(m0 + ldrow) * KTOT + k0 + ldch * 8;
    const __half* Bbase = Wt + (size_t)(n0 + ldrow) * KTOT + k0 + ldch * 8;

    auto load_stage = [&](int s, int kt) {
#pragma unroll
        for (int p = 0; p < 2; p++) {
            int r = ldrow + p * 64;
            uint32_t doff = (uint32_t)(r * 64 + ((ldch ^ ((r >> 1) & 3)) << 4));
            cpasync16(sAu + s * TSTG + doff, Abase + (size_t)p * 64 * KTOT + kt * 32);
            cpasync16(sBu + s * TSTG + doff, Bbase + (size_t)p * 64 * KTOT + kt * 32);
        }
        asm volatile("cp.async.commit_group;" ::: "memory");
    };

    load_stage(0, 0);
    load_stage(1, 1);
    load_stage(2, 2);

    float acc[4][4][4];
#pragma unroll
    for (int i = 0; i < 4; i++)
#pragma unroll
        for (int j = 0; j < 4; j++)
#pragma unroll
            for (int f = 0; f < 4; f++) acc[i][j][f] = 0.0f;

    const int arow0 = wm * 64 + (lane & 15);
    const int acs = lane >> 4;
    const int midx = lane >> 3;
    const int brow0 = wn * 32 + ((midx >> 1) << 3) + (lane & 7);
    const int bcs = midx & 1;

    for (int j = 0; j < NIT; j++) {
        const int s = j % 3;
        asm volatile("cp.async.wait_group 2;" ::: "memory");
        __syncthreads();
        const uint32_t As = sAu + s * TSTG;
        const uint32_t Bs = sBu + s * TSTG;

#pragma unroll
        for (int ks = 0; ks < 2; ks++) {
            uint32_t bf[2][4];
#pragma unroll
            for (int ntp = 0; ntp < 2; ntp++) {
                int r = brow0 + ntp * 16;
                int ch = (ks * 2 + bcs) ^ ((r >> 1) & 3);
                ldmx4(bf[ntp], Bs + (uint32_t)(r * 64 + (ch << 4)));
            }
#pragma unroll
            for (int mt = 0; mt < 4; mt++) {
                int r = arow0 + mt * 16;
                int ch = (ks * 2 + acs) ^ ((r >> 1) & 3);
                uint32_t af[4];
                ldmx4(af, As + (uint32_t)(r * 64 + (ch << 4)));
#pragma unroll
                for (int nt = 0; nt < 4; nt++)
                    mma_f16(acc[mt][nt], af, bf[nt >> 1] + (nt & 1) * 2);
            }
        }

        __syncthreads();
        if (j + 3 < NIT) load_stage(s, j + 3);
    }

    // ---- epilogue ----
    __half* outh = nullptr;
    float* outp = nullptr;
    float scale = 1.0f;
    int h = 0, e0 = 0;
    if (MODE == 0) {
        int which = n0 >> 13;
        outh = (__half*)((which == 0) ? p0 : (which == 1) ? p1 : p2);
        if (which == 0) scale = 0.03125f;   // E^-0.5
        h = (n0 >> 10) & 7;
        e0 = n0 & 1023;
    } else {
        outp = (float*)p0 + (size_t)blockIdx.z * M_ * E_;
    }

#pragma unroll
    for (int mt = 0; mt < 4; mt++) {
#pragma unroll
        for (int half = 0; half < 2; half++) {
            const int m = m0 + wm * 64 + mt * 16 + half * 8 + lr;
            const int b = m >> 6;
#pragma unroll
            for (int nt = 0; nt < 4; nt++) {
                const int nrel = wn * 32 + nt * 8 + lc * 2;
                float v0 = acc[mt][nt][half * 2 + 0];
                float v1 = acc[mt][nt][half * 2 + 1];
                if (MODE == 0) {
                    const int e = e0 + nrel;
                    const int sidx = m & 63;
                    const float* mp = mask + (size_t)b * E_ + e;
                    uint32_t o = packh2(v0 * mp[0] * scale, v1 * mp[1] * scale);
                    *(uint32_t*)(outh +
                        ((size_t)((b * H_ + h) * S_ + sidx)) * E_ + e) = o;
                } else {
                    const int n = n0 + nrel;
                    float2 o; o.x = v0; o.y = v1;
                    *(float2*)(outp + (size_t)m * E_ + n) = o;
                }
            }
        }
    }
}

// ---------------- split-K reduce: out = (sum parts + bias) * mask -----------
__global__ void __launch_bounds__(256) reduce_kernel(
    const float4* __restrict__ part, const float* __restrict__ bias,
    const float* __restrict__ mask, float4* __restrict__ out)
{
    const int i = blockIdx.x * blockDim.x + threadIdx.x;   // float4 index
    if (i >= M_ * E_ / 4) return;
    const int idx = i * 4;
    const int m = idx >> 10;
    const int n = idx & 1023;
    const int b = m >> 6;

    float4 s = part[i];
    float4 p1 = part[i + (M_ * E_ / 4)];
    float4 p2 = part[i + 2 * (M_ * E_ / 4)];
    float4 p3 = part[i + 3 * (M_ * E_ / 4)];
    s.x += p1.x + p2.x + p3.x;
    s.y += p1.y + p2.y + p3.y;
    s.z += p1.z + p2.z + p3.z;
    s.w += p1.w + p2.w + p3.w;

    float4 bv = *(const float4*)(bias + n);
    float4 mv = *(const float4*)(mask + (size_t)b * E_ + n);
    float4 o;
    o.x = (s.x + bv.x) * mv.x;
    o.y = (s.y + bv.y) * mv.y;
    o.z = (s.z + bv.z) * mv.z;
    o.w = (s.w + bv.w) * mv.w;
    out[i] = o;
}

// ---------------- fused attention (one block per (b,h)) ---------------------
#define ATT_SMEM 54272

__global__ void __launch_bounds__(256) attn_fused_kernel(
    const __half* __restrict__ q, const __half* __restrict__ k,
    const __half* __restrict__ v, __half* __restrict__ y)
{
    const int h = blockIdx.x;
    const int b = blockIdx.y;
    const __half* qb = q + (size_t)((b * H_ + h) * S_) * E_;
    const __half* kb = k + (size_t)((b * H_ + h) * S_) * E_;
    const __half* vb = v + (size_t)((b * H_ + h) * S_) * E_;
    __half* yb = y + (size_t)b * S_ * HE_ + h * E_;

    extern __shared__ __align__(16) char sm[];
    const uint32_t sb = s2u(sm);
    const uint32_t sQ[2] = { sb, sb + 9216 };
    const uint32_t sK[2] = { sb + 18432, sb + 27648 };
    float* sL = (float*)(sm + 36864);
    const uint32_t sP = sb;
    const uint32_t sV[2] = { sb + 9216, sb + 26624 };

    const int tid = threadIdx.x;
    const int wid = tid >> 5, lane = tid & 31;
    const int ldr = tid >> 2;
    const int ldc = tid & 3;

    auto loadQK = [&](int s, int kc) {
        const __half* qs = qb + (size_t)ldr * E_ + kc * 64 + ldc * 8;
        const __half* ks = kb + (size_t)ldr * E_ + kc * 64 + ldc * 8;
        uint32_t d = (uint32_t)(ldr * 144 + ldc * 16);
        cpasync16(sQ[s] + d, qs);
        cpasync16(sQ[s] + d + 64, qs + 32);
        cpasync16(sK[s] + d, ks);
        cpasync16(sK[s] + d + 64, ks + 32);
        asm volatile("cp.async.commit_group;" ::: "memory");
    };

    loadQK(0, 0);
    loadQK(1, 1);

    const int wm = wid & 3;
    const int wn = wid >> 2;
    const int arow = wm * 16 + (lane & 15);
    const int acs = lane >> 4;
    const int midx = lane >> 3;
    const int brow = wn * 32 + ((midx >> 1) << 3) + (lane & 7);
    const int bcs = midx & 1;

    float acc[4][4];
#pragma unroll
    for (int i = 0; i < 4; i++)
#pragma unroll
        for (int f = 0; f < 4; f++) acc[i][f] = 0.0f;

    for (int c = 0; c < 16; c++) {
        const int cur = c & 1;
        asm volatile("cp.async.wait_group 1;" ::: "memory");
        __syncthreads();
#pragma unroll
        for (int ks = 0; ks < 4; ks++) {
            uint32_t af[4];
            ldmx4(af, sQ[cur] + (uint32_t)(arow * 144 + ks * 32 + acs * 16));
            uint32_t bf[2][4];
#pragma unroll
            for (int ntp = 0; ntp < 2; ntp++)
                ldmx4(bf[ntp], sK[cur] + (uint32_t)((brow + ntp * 16) * 144 +
                                                    ks * 32 + bcs * 16));
#pragma unroll
            for (int nt = 0; nt < 4; nt++)
                mma_f16(acc[nt], af, bf[nt >> 1] + (nt & 1) * 2);
        }
        __syncthreads();
        if (c + 2 < 16) loadQK(cur, c + 2);
        else asm volatile("cp.async.commit_group;" ::: "memory");
    }

    {
        const int r0 = wm * 16 + (lane >> 2);
        const int cbase = wn * 32 + (lane & 3) * 2;
#pragma unroll
        for (int nt = 0; nt < 4; nt++) {
            sL[(r0)     * 68 + cbase + nt * 8]     = acc[nt][0];
            sL[(r0)     * 68 + cbase + nt * 8 + 1] = acc[nt][1];
            sL[(r0 + 8) * 68 + cbase + nt * 8]     = acc[nt][2];
            sL[(r0 + 8) * 68 + cbase + nt * 8 + 1] = acc[nt][3];
        }
    }
    __syncthreads();

    {
        const int row = tid >> 2;
        const int cb = (tid & 3) * 16;
        float mx = -1e30f;
#pragma unroll
        for (int c = 0; c < 16; c++) mx = fmaxf(mx, sL[row * 68 + cb + c]);
        mx = fmaxf(mx, __shfl_xor_sync(0xffffffffu, mx, 1));
        mx = fmaxf(mx, __shfl_xor_sync(0xffffffffu, mx, 2));
        float ev[16];
        float sum = 0.0f;
#pragma unroll
        for (int c = 0; c < 16; c++) {
            ev[c] = __expf(sL[row * 68 + cb + c] - mx);
            sum += ev[c];
        }
        sum += __shfl_xor_sync(0xffffffffu, sum, 1);
        sum += __shfl_xor_sync(0xffffffffu, sum, 2);
        float inv = 1.0f / sum;
        __syncthreads();
#pragma unroll
        for (int c = 0; c < 8; c++) {
            uint32_t pk = packh2(ev[c * 2] * inv, ev[c * 2 + 1] * inv);
            *(uint32_t*)(sm + (row * 144 + (cb + c * 2) * 2)) = pk;
        }
    }
    __syncthreads();

    auto loadV = [&](int s, int ec) {
        const __half* vs = vb + (size_t)ldr * E_ + ec * 128 + ldc * 8;
        uint32_t d = (uint32_t)(ldr * 272 + ldc * 16);
#pragma unroll
        for (int jj = 0; jj < 4; jj++)
            cpasync16(sV[s] + d + jj * 64, vs + jj * 32);
        asm volatile("cp.async.commit_group;" ::: "memory");
    };

    loadV(0, 0);
    loadV(1, 1);

    const int wm2 = wid & 1;
    const int wn2 = wid >> 1;
    const int prow0 = wm2 * 32 + (lane & 15);
    const int vs0 = ((lane >> 3) & 1) * 8 + (lane & 7);
    const int ve0 = wn2 * 32 + (lane >> 4) * 8;

    for (int ec = 0; ec < 8; ec++) {
        const int cur = ec & 1;
        asm volatile("cp.async.wait_group 1;" ::: "memory");
        __syncthreads();

        float acc2[2][4][4];
#pragma unroll
        for (int i = 0; i < 2; i++)
#pragma unroll
            for (int j = 0; j < 4; j++)
#pragma unroll
                for (int f = 0; f < 4; f++) acc2[i][j][f] = 0.0f;

#pragma unroll
        for (int ks = 0; ks < 4; ks++) {
            uint32_t bf[2][4];
#pragma unroll
            for (int ntp = 0; ntp < 2; ntp++)
                ldmx4t(bf[ntp], sV[cur] + (uint32_t)((ks * 16 + vs0) * 272 +
                                                     (ve0 + ntp * 16) * 2));
#pragma unroll
            for (int mt = 0; mt < 2; mt++) {
                uint32_t af[4];
                ldmx4(af, sP + (uint32_t)((prow0 + mt * 16) * 144 +
                                          ks * 32 + acs * 16));
#pragma unroll
                for (int nt = 0; nt < 4; nt++)
                    mma_f16(acc2[mt][nt], af, bf[nt >> 1] + (nt & 1) * 2);
            }
        }

#pragma unroll
        for (int mt = 0; mt < 2; mt++) {
#pragma unroll
            for (int half = 0; half < 2; half++) {
                const int row = wm2 * 32 + mt * 16 + half * 8 + (lane >> 2);
#pragma unroll
                for (int nt = 0; nt < 4; nt++) {
                    const int col = ec * 128 + wn2 * 32 + nt * 8 + (lane & 3) * 2;
                    uint32_t o = packh2(acc2[mt][nt][half * 2],
                                        acc2[mt][nt][half * 2 + 1]);
                    *(uint32_t*)(yb + (size_t)row * HE_ + col) = o;
                }
            }
        }

        __syncthreads();
        if (ec + 2 < 8) loadV(cur, ec + 2);
        else asm volatile("cp.async.commit_group;" ::: "memory");
    }
}

// ---------------------------------------------------------------------------
extern "C" void kernel_launch(void* const* d_in, const int* in_sizes, int n_in,
                              void* d_out, int out_size)
{
    const float* x    = (const float*)d_in[0];
    const float* mask = (const float*)d_in[1];
    const float* Wq   = (const float*)d_in[2];
    const float* Wk   = (const float*)d_in[3];
    const float* Wv   = (const float*)d_in[4];
    const float* Wo   = (const float*)d_in[5];
    const float* bo   = (const float*)d_in[6];
    float* out = (float*)d_out;

    __half *qh, *kh, *vh, *yh, *xh, *wqkv, *woh;
    float *part;
    cudaGetSymbolAddress((void**)&qh, g_qh);
    cudaGetSymbolAddress((void**)&kh, g_kh);
    cudaGetSymbolAddress((void**)&vh, g_vh);
    cudaGetSymbolAddress((void**)&yh, g_y);
    cudaGetSymbolAddress((void**)&xh, g_xh);
    cudaGetSymbolAddress((void**)&wqkv, g_wqkv);
    cudaGetSymbolAddress((void**)&woh, g_woh);
    cudaGetSymbolAddress((void**)&part, g_part);

    const int SMEM = 6 * TSTG;   // 49152
    static bool attr_set = false;
    if (!attr_set) {
        cudaFuncSetAttribute((const void*)gemm_f16<E_, E_, 0>,
                             cudaFuncAttributeMaxDynamicSharedMemorySize, SMEM);
        cudaFuncSetAttribute((const void*)gemm_f16<HE_, KSPL, 2>,
                             cudaFuncAttributeMaxDynamicSharedMemorySize, SMEM);
        cudaFuncSetAttribute(attn_fused_kernel,
                             cudaFuncAttributeMaxDynamicSharedMemorySize, ATT_SMEM);
        attr_set = true;
    }

    // one fused conversion launch
    cvt_all_kernel<<<(CVT_TOT + 255) / 256, 256>>>(
        (const float4*)x, (const float4*)Wq, (const float4*)Wk,
        (const float4*)Wv, (const float4*)Wo,
        (uint2*)xh, (uint2*)wqkv, (uint2*)woh);

    // fused QKV projection: N = 3*HE = 24576
    dim3 g1(3 * HE_ / 128, M_ / 128);   // (192, 16)
    gemm_f16<E_, E_, 0><<<g1, 256, SMEM>>>(xh, wqkv, mask, qh, kh, vh);

    // fused attention
    attn_fused_kernel<<<dim3(H_, B_), 256, ATT_SMEM>>>(qh, kh, vh, yh);

    // output projection: split-K x4 -> partials -> reduce
    dim3 g2(E_ / 128, M_ / 128, NSPLIT);   // (8, 16, 4) = 512 blocks
    gemm_f16<HE_, KSPL, 2><<<g2, 256, SMEM>>>(yh, woh, mask, part, nullptr, nullptr);

    reduce_kernel<<<(M_ * E_ / 4 + 255) / 256, 256>>>(
        (const float4*)part, bo, mask, (float4*)out);
}

// round 7
// speedup vs baseline: 11.6159x; 1.0281x over previous
#include <cuda_runtime.h>
#include <cuda_fp16.h>
#include <cstdint>

#define B_ 32
#define S_ 64
#define H_ 8
#define E_ 1024
#define HE_ 8192
#define M_ 2048
#define NSPLIT 4
#define KSPL (HE_ / NSPLIT)   // 2048

// ---------------- scratch (__device__ globals) ------------------------------
__device__ __half g_qh[B_ * H_ * S_ * E_];
__device__ __half g_kh[B_ * H_ * S_ * E_];
__device__ __half g_vh[B_ * H_ * S_ * E_];
__device__ __half g_y[M_ * HE_];
__device__ __half g_xh[M_ * E_];
__device__ __half g_wqkv[3 * HE_ * E_];
__device__ __half g_woh[E_ * HE_];
__device__ float  g_part[NSPLIT * M_ * E_];

// ---------------- helpers ---------------------------------------------------
__device__ __forceinline__ uint32_t s2u(const void* p) {
    uint32_t a;
    asm("{ .reg .u64 t; cvta.to.shared.u64 t, %1; cvt.u32.u64 %0, t; }"
        : "=r"(a) : "l"(p));
    return a;
}

__device__ __forceinline__ void cpasync16(uint32_t dst, const void* src) {
    asm volatile("cp.async.cg.shared.global [%0], [%1], 16;" :: "r"(dst), "l"(src));
}

__device__ __forceinline__ uint32_t packh2(float a, float b) {
    __half2 h = __floats2half2_rn(a, b);
    return *reinterpret_cast<uint32_t*>(&h);
}

__device__ __forceinline__ void ldmx4(uint32_t* r, uint32_t addr) {
    asm volatile("ldmatrix.sync.aligned.m8n8.x4.shared.b16 {%0,%1,%2,%3}, [%4];"
                 : "=r"(r[0]), "=r"(r[1]), "=r"(r[2]), "=r"(r[3]) : "r"(addr));
}

__device__ __forceinline__ void ldmx4t(uint32_t* r, uint32_t addr) {
    asm volatile("ldmatrix.sync.aligned.m8n8.x4.trans.shared.b16 {%0,%1,%2,%3}, [%4];"
                 : "=r"(r[0]), "=r"(r[1]), "=r"(r[2]), "=r"(r[3]) : "r"(addr));
}

__device__ __forceinline__ void mma_f16(float* d, const uint32_t* a,
                                        const uint32_t* b) {
    asm volatile(
        "mma.sync.aligned.m16n8k16.row.col.f32.f16.f16.f32 "
        "{%0,%1,%2,%3}, {%4,%5,%6,%7}, {%8,%9}, {%0,%1,%2,%3};"
        : "+f"(d[0]), "+f"(d[1]), "+f"(d[2]), "+f"(d[3])
        : "r"(a[0]), "r"(a[1]), "r"(a[2]), "r"(a[3]), "r"(b[0]), "r"(b[1]));
}

// ---------------- fused fp32->fp16 conversion -------------------------------
#define N4X  (M_ * E_ / 4)
#define N4W  (HE_ * E_ / 4)
__global__ void __launch_bounds__(256) cvt_all_kernel(
    const float4* __restrict__ x,
    const float4* __restrict__ wq, const float4* __restrict__ wk,
    const float4* __restrict__ wv, const float4* __restrict__ wo,
    uint2* __restrict__ xh, uint2* __restrict__ wqkvh, uint2* __restrict__ woh)
{
    int i = blockIdx.x * blockDim.x + threadIdx.x;
    const float4* src;
    uint2* dst;
    if (i < N4X)                { src = x + i;               dst = xh + i; }
    else if (i < N4X + N4W)     { int j = i - N4X;           src = wq + j; dst = wqkvh + j; }
    else if (i < N4X + 2 * N4W) { int j = i - N4X - N4W;     src = wk + j; dst = wqkvh + N4W + j; }
    else if (i < N4X + 3 * N4W) { int j = i - N4X - 2 * N4W; src = wv + j; dst = wqkvh + 2 * N4W + j; }
    else if (i < N4X + 4 * N4W) { int j = i - N4X - 3 * N4W; src = wo + j; dst = woh + j; }
    else return;
    float4 v = *src;
    uint2 o;
    o.x = packh2(v.x, v.y);
    o.y = packh2(v.z, v.w);
    *dst = o;
}
#define CVT_TOT (N4X + 4 * N4W)

// ---------------- fp16 tensor-core GEMM (NT), 4-stage single-sync -----------
// MODE 0 (fused QKV, fp16 out): n0 selects {q,k,v}+head; val*mask*scale.
// MODE 2 (split-K partial): fp32 partial into slice blockIdx.z.
#define TSTG 8192
#define NSTAGE 4

template<int KTOT, int KITER, int MODE>
__global__ void __launch_bounds__(256) gemm_f16(
    const __half* __restrict__ A, const __half* __restrict__ Wt,
    const float* __restrict__ mask,
    void* __restrict__ p0, void* __restrict__ p1, void* __restrict__ p2)
{
    constexpr int NIT = KITER / 32;
    extern __shared__ __align__(16) char sm[];
    const uint32_t sAu = s2u(sm);
    const uint32_t sBu = sAu + NSTAGE * TSTG;

    const int tid = threadIdx.x;
    const int wid = tid >> 5, lane = tid & 31;
    const int wm = wid & 1;
    const int wn = wid >> 1;
    const int lr = lane >> 2;
    const int lc = lane & 3;
    const int m0 = blockIdx.y * 128;
    const int n0 = blockIdx.x * 128;
    const int k0 = (MODE == 2) ? blockIdx.z * KITER : 0;

    const int ldrow = tid >> 2;
    const int ldch = tid & 3;
    const __half* Abase = A + (size_t)(m0 + ldrow) * KTOT + k0 + ldch * 8;
    const __half* Bbase = Wt + (size_t)(n0 + ldrow) * KTOT + k0 + ldch * 8;

    auto load_stage = [&](int s, int kt) {
#pragma unroll
        for (int p = 0; p < 2; p++) {
            int r = ldrow + p * 64;
            uint32_t doff = (uint32_t)(r * 64 + ((ldch ^ ((r >> 1) & 3)) << 4));
            cpasync16(sAu + s * TSTG + doff, Abase + (size_t)p * 64 * KTOT + kt * 32);
            cpasync16(sBu + s * TSTG + doff, Bbase + (size_t)p * 64 * KTOT + kt * 32);
        }
        asm volatile("cp.async.commit_group;" ::: "memory");
    };

    load_stage(0, 0);
    load_stage(1, 1);
    load_stage(2, 2);

    float acc[4][4][4];
#pragma unroll
    for (int i = 0; i < 4; i++)
#pragma unroll
        for (int j = 0; j < 4; j++)
#pragma unroll
            for (int f = 0; f < 4; f++) acc[i][j][f] = 0.0f;

    const int arow0 = wm * 64 + (lane & 15);
    const int acs = lane >> 4;
    const int midx = lane >> 3;
    const int brow0 = wn * 32 + ((midx >> 1) << 3) + (lane & 7);
    const int bcs = midx & 1;

    for (int j = 0; j < NIT; j++) {
        const int s = j & (NSTAGE - 1);
        asm volatile("cp.async.wait_group 2;" ::: "memory");
        __syncthreads();
        // 4 stages: (j+3)%4 == (j-1)%4, whose readers all passed the barrier.
        if (j + 3 < NIT) load_stage((j + 3) & (NSTAGE - 1), j + 3);

        const uint32_t As = sAu + s * TSTG;
        const uint32_t Bs = sBu + s * TSTG;

#pragma unroll
        for (int ks = 0; ks < 2; ks++) {
            uint32_t bf[2][4];
#pragma unroll
            for (int ntp = 0; ntp < 2; ntp++) {
                int r = brow0 + ntp * 16;
                int ch = (ks * 2 + bcs) ^ ((r >> 1) & 3);
                ldmx4(bf[ntp], Bs + (uint32_t)(r * 64 + (ch << 4)));
            }
#pragma unroll
            for (int mt = 0; mt < 4; mt++) {
                int r = arow0 + mt * 16;
                int ch = (ks * 2 + acs) ^ ((r >> 1) & 3);
                uint32_t af[4];
                ldmx4(af, As + (uint32_t)(r * 64 + (ch << 4)));
#pragma unroll
                for (int nt = 0; nt < 4; nt++)
                    mma_f16(acc[mt][nt], af, bf[nt >> 1] + (nt & 1) * 2);
            }
        }
    }

    // ---- epilogue ----
    __half* outh = nullptr;
    float* outp = nullptr;
    float scale = 1.0f;
    int h = 0, e0 = 0;
    if (MODE == 0) {
        int which = n0 >> 13;
        outh = (__half*)((which == 0) ? p0 : (which == 1) ? p1 : p2);
        if (which == 0) scale = 0.03125f;   // E^-0.5
        h = (n0 >> 10) & 7;
        e0 = n0 & 1023;
    } else {
        outp = (float*)p0 + (size_t)blockIdx.z * M_ * E_;
    }

#pragma unroll
    for (int mt = 0; mt < 4; mt++) {
#pragma unroll
        for (int half = 0; half < 2; half++) {
            const int m = m0 + wm * 64 + mt * 16 + half * 8 + lr;
            const int b = m >> 6;
#pragma unroll
            for (int nt = 0; nt < 4; nt++) {
                const int nrel = wn * 32 + nt * 8 + lc * 2;
                float v0 = acc[mt][nt][half * 2 + 0];
                float v1 = acc[mt][nt][half * 2 + 1];
                if (MODE == 0) {
                    const int e = e0 + nrel;
                    const int sidx = m & 63;
                    const float* mp = mask + (size_t)b * E_ + e;
                    uint32_t o = packh2(v0 * mp[0] * scale, v1 * mp[1] * scale);
                    *(uint32_t*)(outh +
                        ((size_t)((b * H_ + h) * S_ + sidx)) * E_ + e) = o;
                } else {
                    const int n = n0 + nrel;
                    float2 o; o.x = v0; o.y = v1;
                    *(float2*)(outp + (size_t)m * E_ + n) = o;
                }
            }
        }
    }
}

// ---------------- split-K reduce: out = (sum parts + bias) * mask -----------
__global__ void __launch_bounds__(256) reduce_kernel(
    const float4* __restrict__ part, const float* __restrict__ bias,
    const float* __restrict__ mask, float4* __restrict__ out)
{
    const int i = blockIdx.x * blockDim.x + threadIdx.x;
    if (i >= M_ * E_ / 4) return;
    const int idx = i * 4;
    const int m = idx >> 10;
    const int n = idx & 1023;
    const int b = m >> 6;

    float4 s = part[i];
    float4 p1 = part[i + (M_ * E_ / 4)];
    float4 p2 = part[i + 2 * (M_ * E_ / 4)];
    float4 p3 = part[i + 3 * (M_ * E_ / 4)];
    s.x += p1.x + p2.x + p3.x;
    s.y += p1.y + p2.y + p3.y;
    s.z += p1.z + p2.z + p3.z;
    s.w += p1.w + p2.w + p3.w;

    float4 bv = *(const float4*)(bias + n);
    float4 mv = *(const float4*)(mask + (size_t)b * E_ + n);
    float4 o;
    o.x = (s.x + bv.x) * mv.x;
    o.y = (s.y + bv.y) * mv.y;
    o.z = (s.z + bv.z) * mv.z;
    o.w = (s.w + bv.w) * mv.w;
    out[i] = o;
}

// ---------------- fused attention (one block per (b,h)) ---------------------
#define ATT_SMEM 54272

__global__ void __launch_bounds__(256) attn_fused_kernel(
    const __half* __restrict__ q, const __half* __restrict__ k,
    const __half* __restrict__ v, __half* __restrict__ y)
{
    const int h = blockIdx.x;
    const int b = blockIdx.y;
    const __half* qb = q + (size_t)((b * H_ + h) * S_) * E_;
    const __half* kb = k + (size_t)((b * H_ + h) * S_) * E_;
    const __half* vb = v + (size_t)((b * H_ + h) * S_) * E_;
    __half* yb = y + (size_t)b * S_ * HE_ + h * E_;

    extern __shared__ __align__(16) char sm[];
    const uint32_t sb = s2u(sm);
    const uint32_t sQ[2] = { sb, sb + 9216 };
    const uint32_t sK[2] = { sb + 18432, sb + 27648 };
    float* sL = (float*)(sm + 36864);
    const uint32_t sP = sb;
    const uint32_t sV[2] = { sb + 9216, sb + 26624 };

    const int tid = threadIdx.x;
    const int wid = tid >> 5, lane = tid & 31;
    const int ldr = tid >> 2;
    const int ldc = tid & 3;

    auto loadQK = [&](int s, int kc) {
        const __half* qs = qb + (size_t)ldr * E_ + kc * 64 + ldc * 8;
        const __half* ks = kb + (size_t)ldr * E_ + kc * 64 + ldc * 8;
        uint32_t d = (uint32_t)(ldr * 144 + ldc * 16);
        cpasync16(sQ[s] + d, qs);
        cpasync16(sQ[s] + d + 64, qs + 32);
        cpasync16(sK[s] + d, ks);
        cpasync16(sK[s] + d + 64, ks + 32);
        asm volatile("cp.async.commit_group;" ::: "memory");
    };

    loadQK(0, 0);
    loadQK(1, 1);

    const int wm = wid & 3;
    const int wn = wid >> 2;
    const int arow = wm * 16 + (lane & 15);
    const int acs = lane >> 4;
    const int midx = lane >> 3;
    const int brow = wn * 32 + ((midx >> 1) << 3) + (lane & 7);
    const int bcs = midx & 1;

    float acc[4][4];
#pragma unroll
    for (int i = 0; i < 4; i++)
#pragma unroll
        for (int f = 0; f < 4; f++) acc[i][f] = 0.0f;

    for (int c = 0; c < 16; c++) {
        const int cur = c & 1;
        asm volatile("cp.async.wait_group 1;" ::: "memory");
        __syncthreads();
#pragma unroll
        for (int ks = 0; ks < 4; ks++) {
            uint32_t af[4];
            ldmx4(af, sQ[cur] + (uint32_t)(arow * 144 + ks * 32 + acs * 16));
            uint32_t bf[2][4];
#pragma unroll
            for (int ntp = 0; ntp < 2; ntp++)
                ldmx4(bf[ntp], sK[cur] + (uint32_t)((brow + ntp * 16) * 144 +
                                                    ks * 32 + bcs * 16));
#pragma unroll
            for (int nt = 0; nt < 4; nt++)
                mma_f16(acc[nt], af, bf[nt >> 1] + (nt & 1) * 2);
        }
        __syncthreads();
        if (c + 2 < 16) loadQK(cur, c + 2);
        else asm volatile("cp.async.commit_group;" ::: "memory");
    }

    {
        const int r0 = wm * 16 + (lane >> 2);
        const int cbase = wn * 32 + (lane & 3) * 2;
#pragma unroll
        for (int nt = 0; nt < 4; nt++) {
            sL[(r0)     * 68 + cbase + nt * 8]     = acc[nt][0];
            sL[(r0)     * 68 + cbase + nt * 8 + 1] = acc[nt][1];
            sL[(r0 + 8) * 68 + cbase + nt * 8]     = acc[nt][2];
            sL[(r0 + 8) * 68 + cbase + nt * 8 + 1] = acc[nt][3];
        }
    }
    __syncthreads();

    {
        const int row = tid >> 2;
        const int cb = (tid & 3) * 16;
        float mx = -1e30f;
#pragma unroll
        for (int c = 0; c < 16; c++) mx = fmaxf(mx, sL[row * 68 + cb + c]);
        mx = fmaxf(mx, __shfl_xor_sync(0xffffffffu, mx, 1));
        mx = fmaxf(mx, __shfl_xor_sync(0xffffffffu, mx, 2));
        float ev[16];
        float sum = 0.0f;
#pragma unroll
        for (int c = 0; c < 16; c++) {
            ev[c] = __expf(sL[row * 68 + cb + c] - mx);
            sum += ev[c];
        }
        sum += __shfl_xor_sync(0xffffffffu, sum, 1);
        sum += __shfl_xor_sync(0xffffffffu, sum, 2);
        float inv = 1.0f / sum;
        __syncthreads();
#pragma unroll
        for (int c = 0; c < 8; c++) {
            uint32_t pk = packh2(ev[c * 2] * inv, ev[c * 2 + 1] * inv);
            *(uint32_t*)(sm + (row * 144 + (cb + c * 2) * 2)) = pk;
        }
    }
    __syncthreads();

    auto loadV = [&](int s, int ec) {
        const __half* vs = vb + (size_t)ldr * E_ + ec * 128 + ldc * 8;
        uint32_t d = (uint32_t)(ldr * 272 + ldc * 16);
#pragma unroll
        for (int jj = 0; jj < 4; jj++)
            cpasync16(sV[s] + d + jj * 64, vs + jj * 32);
        asm volatile("cp.async.commit_group;" ::: "memory");
    };

    loadV(0, 0);
    loadV(1, 1);

    const int wm2 = wid & 1;
    const int wn2 = wid >> 1;
    const int prow0 = wm2 * 32 + (lane & 15);
    const int vs0 = ((lane >> 3) & 1) * 8 + (lane & 7);
    const int ve0 = wn2 * 32 + (lane >> 4) * 8;

    for (int ec = 0; ec < 8; ec++) {
        const int cur = ec & 1;
        asm volatile("cp.async.wait_group 1;" ::: "memory");
        __syncthreads();

        float acc2[2][4][4];
#pragma unroll
        for (int i = 0; i < 2; i++)
#pragma unroll
            for (int j = 0; j < 4; j++)
#pragma unroll
                for (int f = 0; f < 4; f++) acc2[i][j][f] = 0.0f;

#pragma unroll
        for (int ks = 0; ks < 4; ks++) {
            uint32_t bf[2][4];
#pragma unroll
            for (int ntp = 0; ntp < 2; ntp++)
                ldmx4t(bf[ntp], sV[cur] + (uint32_t)((ks * 16 + vs0) * 272 +
                                                     (ve0 + ntp * 16) * 2));
#pragma unroll
            for (int mt = 0; mt < 2; mt++) {
                uint32_t af[4];
                ldmx4(af, sP + (uint32_t)((prow0 + mt * 16) * 144 +
                                          ks * 32 + acs * 16));
#pragma unroll
                for (int nt = 0; nt < 4; nt++)
                    mma_f16(acc2[mt][nt], af, bf[nt >> 1] + (nt & 1) * 2);
            }
        }

#pragma unroll
        for (int mt = 0; mt < 2; mt++) {
#pragma unroll
            for (int half = 0; half < 2; half++) {
                const int row = wm2 * 32 + mt * 16 + half * 8 + (lane >> 2);
#pragma unroll
                for (int nt = 0; nt < 4; nt++) {
                    const int col = ec * 128 + wn2 * 32 + nt * 8 + (lane & 3) * 2;
                    uint32_t o = packh2(acc2[mt][nt][half * 2],
                                        acc2[mt][nt][half * 2 + 1]);
                    *(uint32_t*)(yb + (size_t)row * HE_ + col) = o;
                }
            }
        }

        __syncthreads();
        if (ec + 2 < 8) loadV(cur, ec + 2);
        else asm volatile("cp.async.commit_group;" ::: "memory");
    }
}

// ---------------------------------------------------------------------------
extern "C" void kernel_launch(void* const* d_in, const int* in_sizes, int n_in,
                              void* d_out, int out_size)
{
    const float* x    = (const float*)d_in[0];
    const float* mask = (const float*)d_in[1];
    const float* Wq   = (const float*)d_in[2];
    const float* Wk   = (const float*)d_in[3];
    const float* Wv   = (const float*)d_in[4];
    const float* Wo   = (const float*)d_in[5];
    const float* bo   = (const float*)d_in[6];
    float* out = (float*)d_out;

    __half *qh, *kh, *vh, *yh, *xh, *wqkv, *woh;
    float *part;
    cudaGetSymbolAddress((void**)&qh, g_qh);
    cudaGetSymbolAddress((void**)&kh, g_kh);
    cudaGetSymbolAddress((void**)&vh, g_vh);
    cudaGetSymbolAddress((void**)&yh, g_y);
    cudaGetSymbolAddress((void**)&xh, g_xh);
    cudaGetSymbolAddress((void**)&wqkv, g_wqkv);
    cudaGetSymbolAddress((void**)&woh, g_woh);
    cudaGetSymbolAddress((void**)&part, g_part);

    const int SMEM = 2 * NSTAGE * TSTG;   // 65536
    static bool attr_set = false;
    if (!attr_set) {
        cudaFuncSetAttribute((const void*)gemm_f16<E_, E_, 0>,
                             cudaFuncAttributeMaxDynamicSharedMemorySize, SMEM);
        cudaFuncSetAttribute((const void*)gemm_f16<HE_, KSPL, 2>,
                             cudaFuncAttributeMaxDynamicSharedMemorySize, SMEM);
        cudaFuncSetAttribute(attn_fused_kernel,
                             cudaFuncAttributeMaxDynamicSharedMemorySize, ATT_SMEM);
        attr_set = true;
    }

    cvt_all_kernel<<<(CVT_TOT + 255) / 256, 256>>>(
        (const float4*)x, (const float4*)Wq, (const float4*)Wk,
        (const float4*)Wv, (const float4*)Wo,
        (uint2*)xh, (uint2*)wqkv, (uint2*)woh);

    dim3 g1(3 * HE_ / 128, M_ / 128);   // (192, 16)
    gemm_f16<E_, E_, 0><<<g1, 256, SMEM>>>(xh, wqkv, mask, qh, kh, vh);

    attn_fused_kernel<<<dim3(H_, B_), 256, ATT_SMEM>>>(qh, kh, vh, yh);

    dim3 g2(E_ / 128, M_ / 128, NSPLIT);   // (8, 16, 4) = 512 blocks
    gemm_f16<HE_, KSPL, 2><<<g2, 256, SMEM>>>(yh, woh, mask, part, nullptr, nullptr);

    reduce_kernel<<<(M_ * E_ / 4 + 255) / 256, 256>>>(
        (const float4*)part, bo, mask, (float4*)out);
}

// round 8
// speedup vs baseline: 13.2656x; 1.1420x over previous
#include <cuda_runtime.h>
#include <cuda_fp16.h>
#include <cstdint>

#define B_ 32
#define S_ 64
#define H_ 8
#define E_ 1024
#define HE_ 8192
#define M_ 2048
#define NSPLIT 4
#define KSPL (HE_ / NSPLIT)   // 2048

// ---------------- scratch (__device__ globals) ------------------------------
__device__ __half g_qh[B_ * H_ * S_ * E_];
__device__ __half g_kh[B_ * H_ * S_ * E_];
__device__ __half g_vh[B_ * H_ * S_ * E_];
__device__ __half g_y[M_ * HE_];
__device__ __half g_xh[M_ * E_];
__device__ __half g_wqkv[3 * HE_ * E_];
__device__ __half g_woh[E_ * HE_];
__device__ float  g_part[NSPLIT * M_ * E_];

// ---------------- helpers ---------------------------------------------------
__device__ __forceinline__ uint32_t s2u(const void* p) {
    uint32_t a;
    asm("{ .reg .u64 t; cvta.to.shared.u64 t, %1; cvt.u32.u64 %0, t; }"
        : "=r"(a) : "l"(p));
    return a;
}

__device__ __forceinline__ void cpasync16(uint32_t dst, const void* src) {
    asm volatile("cp.async.cg.shared.global [%0], [%1], 16;" :: "r"(dst), "l"(src));
}

__device__ __forceinline__ uint32_t packh2(float a, float b) {
    __half2 h = __floats2half2_rn(a, b);
    return *reinterpret_cast<uint32_t*>(&h);
}

__device__ __forceinline__ void ldmx4(uint32_t* r, uint32_t addr) {
    asm volatile("ldmatrix.sync.aligned.m8n8.x4.shared.b16 {%0,%1,%2,%3}, [%4];"
                 : "=r"(r[0]), "=r"(r[1]), "=r"(r[2]), "=r"(r[3]) : "r"(addr));
}

__device__ __forceinline__ void ldmx4t(uint32_t* r, uint32_t addr) {
    asm volatile("ldmatrix.sync.aligned.m8n8.x4.trans.shared.b16 {%0,%1,%2,%3}, [%4];"
                 : "=r"(r[0]), "=r"(r[1]), "=r"(r[2]), "=r"(r[3]) : "r"(addr));
}

__device__ __forceinline__ void mma_f16(float* d, const uint32_t* a,
                                        const uint32_t* b) {
    asm volatile(
        "mma.sync.aligned.m16n8k16.row.col.f32.f16.f16.f32 "
        "{%0,%1,%2,%3}, {%4,%5,%6,%7}, {%8,%9}, {%0,%1,%2,%3};"
        : "+f"(d[0]), "+f"(d[1]), "+f"(d[2]), "+f"(d[3])
        : "r"(a[0]), "r"(a[1]), "r"(a[2]), "r"(a[3]), "r"(b[0]), "r"(b[1]));
}

// ---------------- fused fp32->fp16 conversion -------------------------------
#define N4X  (M_ * E_ / 4)
#define N4W  (HE_ * E_ / 4)
__global__ void __launch_bounds__(256) cvt_all_kernel(
    const float4* __restrict__ x,
    const float4* __restrict__ wq, const float4* __restrict__ wk,
    const float4* __restrict__ wv, const float4* __restrict__ wo,
    uint2* __restrict__ xh, uint2* __restrict__ wqkvh, uint2* __restrict__ woh)
{
    int i = blockIdx.x * blockDim.x + threadIdx.x;
    const float4* src;
    uint2* dst;
    if (i < N4X)                { src = x + i;               dst = xh + i; }
    else if (i < N4X + N4W)     { int j = i - N4X;           src = wq + j; dst = wqkvh + j; }
    else if (i < N4X + 2 * N4W) { int j = i - N4X - N4W;     src = wk + j; dst = wqkvh + N4W + j; }
    else if (i < N4X + 3 * N4W) { int j = i - N4X - 2 * N4W; src = wv + j; dst = wqkvh + 2 * N4W + j; }
    else if (i < N4X + 4 * N4W) { int j = i - N4X - 3 * N4W; src = wo + j; dst = woh + j; }
    else return;
    float4 v = *src;
    uint2 o;
    o.x = packh2(v.x, v.y);
    o.y = packh2(v.z, v.w);
    *dst = o;
}
#define CVT_TOT (N4X + 4 * N4W)

// ---------------- fp16 tensor-core GEMM (NT), 4 warps, 64x64 warp tile ------
// CTA tile 128x128x32, 128 threads, 4-stage cp.async, single sync per iter.
// MODE 0 (fused QKV, fp16 out): n0 selects {q,k,v}+head; val*mask*scale.
// MODE 2 (split-K partial): fp32 partial into slice blockIdx.z.
#define TSTG 8192
#define NSTAGE 4

template<int KTOT, int KITER, int MODE>
__global__ void __launch_bounds__(128) gemm_f16(
    const __half* __restrict__ A, const __half* __restrict__ Wt,
    const float* __restrict__ mask,
    void* __restrict__ p0, void* __restrict__ p1, void* __restrict__ p2)
{
    constexpr int NIT = KITER / 32;
    extern __shared__ __align__(16) char sm[];
    const uint32_t sAu = s2u(sm);
    const uint32_t sBu = sAu + NSTAGE * TSTG;

    const int tid = threadIdx.x;
    const int wid = tid >> 5, lane = tid & 31;
    const int wm = wid & 1;          // 64-row group
    const int wn = wid >> 1;         // 64-col group
    const int lr = lane >> 2;
    const int lc = lane & 3;
    const int m0 = blockIdx.y * 128;
    const int n0 = blockIdx.x * 128;
    const int k0 = (MODE == 2) ? blockIdx.z * KITER : 0;

    // loader: 128 thr, 4 passes x (row = tid>>2 + p*32, chunk = tid&3)
    const int ldrow = tid >> 2;      // 0..31
    const int ldch = tid & 3;
    const __half* Abase = A + (size_t)(m0 + ldrow) * KTOT + k0 + ldch * 8;
    const __half* Bbase = Wt + (size_t)(n0 + ldrow) * KTOT + k0 + ldch * 8;

    auto load_stage = [&](int s, int kt) {
#pragma unroll
        for (int p = 0; p < 4; p++) {
            int r = ldrow + p * 32;
            uint32_t doff = (uint32_t)(r * 64 + ((ldch ^ ((r >> 1) & 3)) << 4));
            cpasync16(sAu + s * TSTG + doff, Abase + (size_t)p * 32 * KTOT + kt * 32);
            cpasync16(sBu + s * TSTG + doff, Bbase + (size_t)p * 32 * KTOT + kt * 32);
        }
        asm volatile("cp.async.commit_group;" ::: "memory");
    };

    load_stage(0, 0);
    load_stage(1, 1);
    load_stage(2, 2);

    float acc[4][8][4];              // [mt][nt][frag] = 128 regs
#pragma unroll
    for (int i = 0; i < 4; i++)
#pragma unroll
        for (int j = 0; j < 8; j++)
#pragma unroll
            for (int f = 0; f < 4; f++) acc[i][j][f] = 0.0f;

    const int arow0 = wm * 64 + (lane & 15);
    const int acs = lane >> 4;
    const int midx = lane >> 3;
    const int brow0 = wn * 64 + ((midx >> 1) << 3) + (lane & 7);
    const int bcs = midx & 1;

    for (int j = 0; j < NIT; j++) {
        const int s = j & (NSTAGE - 1);
        asm volatile("cp.async.wait_group 2;" ::: "memory");
        __syncthreads();
        if (j + 3 < NIT) load_stage((j + 3) & (NSTAGE - 1), j + 3);

        const uint32_t As = sAu + s * TSTG;
        const uint32_t Bs = sBu + s * TSTG;

#pragma unroll
        for (int ks = 0; ks < 2; ks++) {
            uint32_t bf[4][4];
#pragma unroll
            for (int ntp = 0; ntp < 4; ntp++) {
                int r = brow0 + ntp * 16;
                int ch = (ks * 2 + bcs) ^ ((r >> 1) & 3);
                ldmx4(bf[ntp], Bs + (uint32_t)(r * 64 + (ch << 4)));
            }
#pragma unroll
            for (int mt = 0; mt < 4; mt++) {
                int r = arow0 + mt * 16;
                int ch = (ks * 2 + acs) ^ ((r >> 1) & 3);
                uint32_t af[4];
                ldmx4(af, As + (uint32_t)(r * 64 + (ch << 4)));
#pragma unroll
                for (int nt = 0; nt < 8; nt++)
                    mma_f16(acc[mt][nt], af, bf[nt >> 1] + (nt & 1) * 2);
            }
        }
    }

    // ---- epilogue ----
    __half* outh = nullptr;
    float* outp = nullptr;
    float scale = 1.0f;
    int h = 0, e0 = 0;
    if (MODE == 0) {
        int which = n0 >> 13;
        outh = (__half*)((which == 0) ? p0 : (which == 1) ? p1 : p2);
        if (which == 0) scale = 0.03125f;   // E^-0.5
        h = (n0 >> 10) & 7;
        e0 = n0 & 1023;
    } else {
        outp = (float*)p0 + (size_t)blockIdx.z * M_ * E_;
    }

#pragma unroll
    for (int mt = 0; mt < 4; mt++) {
#pragma unroll
        for (int half = 0; half < 2; half++) {
            const int m = m0 + wm * 64 + mt * 16 + half * 8 + lr;
            const int b = m >> 6;
#pragma unroll
            for (int nt = 0; nt < 8; nt++) {
                const int nrel = wn * 64 + nt * 8 + lc * 2;
                float v0 = acc[mt][nt][half * 2 + 0];
                float v1 = acc[mt][nt][half * 2 + 1];
                if (MODE == 0) {
                    const int e = e0 + nrel;
                    const int sidx = m & 63;
                    const float* mp = mask + (size_t)b * E_ + e;
                    uint32_t o = packh2(v0 * mp[0] * scale, v1 * mp[1] * scale);
                    *(uint32_t*)(outh +
                        ((size_t)((b * H_ + h) * S_ + sidx)) * E_ + e) = o;
                } else {
                    const int n = n0 + nrel;
                    float2 o; o.x = v0; o.y = v1;
                    *(float2*)(outp + (size_t)m * E_ + n) = o;
                }
            }
        }
    }
}

// ---------------- split-K reduce: out = (sum parts + bias) * mask -----------
__global__ void __launch_bounds__(256) reduce_kernel(
    const float4* __restrict__ part, const float* __restrict__ bias,
    const float* __restrict__ mask, float4* __restrict__ out)
{
    const int i = blockIdx.x * blockDim.x + threadIdx.x;
    if (i >= M_ * E_ / 4) return;
    const int idx = i * 4;
    const int m = idx >> 10;
    const int n = idx & 1023;
    const int b = m >> 6;

    float4 s = part[i];
    float4 p1 = part[i + (M_ * E_ / 4)];
    float4 p2 = part[i + 2 * (M_ * E_ / 4)];
    float4 p3 = part[i + 3 * (M_ * E_ / 4)];
    s.x += p1.x + p2.x + p3.x;
    s.y += p1.y + p2.y + p3.y;
    s.z += p1.z + p2.z + p3.z;
    s.w += p1.w + p2.w + p3.w;

    float4 bv = *(const float4*)(bias + n);
    float4 mv = *(const float4*)(mask + (size_t)b * E_ + n);
    float4 o;
    o.x = (s.x + bv.x) * mv.x;
    o.y = (s.y + bv.y) * mv.y;
    o.z = (s.z + bv.z) * mv.z;
    o.w = (s.w + bv.w) * mv.w;
    out[i] = o;
}

// ---------------- fused attention (one block per (b,h)) ---------------------
#define ATT_SMEM 54272

__global__ void __launch_bounds__(256) attn_fused_kernel(
    const __half* __restrict__ q, const __half* __restrict__ k,
    const __half* __restrict__ v, __half* __restrict__ y)
{
    const int h = blockIdx.x;
    const int b = blockIdx.y;
    const __half* qb = q + (size_t)((b * H_ + h) * S_) * E_;
    const __half* kb = k + (size_t)((b * H_ + h) * S_) * E_;
    const __half* vb = v + (size_t)((b * H_ + h) * S_) * E_;
    __half* yb = y + (size_t)b * S_ * HE_ + h * E_;

    extern __shared__ __align__(16) char sm[];
    const uint32_t sb = s2u(sm);
    const uint32_t sQ[2] = { sb, sb + 9216 };
    const uint32_t sK[2] = { sb + 18432, sb + 27648 };
    float* sL = (float*)(sm + 36864);
    const uint32_t sP = sb;
    const uint32_t sV[2] = { sb + 9216, sb + 26624 };

    const int tid = threadIdx.x;
    const int wid = tid >> 5, lane = tid & 31;
    const int ldr = tid >> 2;
    const int ldc = tid & 3;

    auto loadQK = [&](int s, int kc) {
        const __half* qs = qb + (size_t)ldr * E_ + kc * 64 + ldc * 8;
        const __half* ks = kb + (size_t)ldr * E_ + kc * 64 + ldc * 8;
        uint32_t d = (uint32_t)(ldr * 144 + ldc * 16);
        cpasync16(sQ[s] + d, qs);
        cpasync16(sQ[s] + d + 64, qs + 32);
        cpasync16(sK[s] + d, ks);
        cpasync16(sK[s] + d + 64, ks + 32);
        asm volatile("cp.async.commit_group;" ::: "memory");
    };

    loadQK(0, 0);
    loadQK(1, 1);

    const int wm = wid & 3;
    const int wn = wid >> 2;
    const int arow = wm * 16 + (lane & 15);
    const int acs = lane >> 4;
    const int midx = lane >> 3;
    const int brow = wn * 32 + ((midx >> 1) << 3) + (lane & 7);
    const int bcs = midx & 1;

    float acc[4][4];
#pragma unroll
    for (int i = 0; i < 4; i++)
#pragma unroll
        for (int f = 0; f < 4; f++) acc[i][f] = 0.0f;

    for (int c = 0; c < 16; c++) {
        const int cur = c & 1;
        asm volatile("cp.async.wait_group 1;" ::: "memory");
        __syncthreads();
#pragma unroll
        for (int ks = 0; ks < 4; ks++) {
            uint32_t af[4];
            ldmx4(af, sQ[cur] + (uint32_t)(arow * 144 + ks * 32 + acs * 16));
            uint32_t bf[2][4];
#pragma unroll
            for (int ntp = 0; ntp < 2; ntp++)
                ldmx4(bf[ntp], sK[cur] + (uint32_t)((brow + ntp * 16) * 144 +
                                                    ks * 32 + bcs * 16));
#pragma unroll
            for (int nt = 0; nt < 4; nt++)
                mma_f16(acc[nt], af, bf[nt >> 1] + (nt & 1) * 2);
        }
        __syncthreads();
        if (c + 2 < 16) loadQK(cur, c + 2);
        else asm volatile("cp.async.commit_group;" ::: "memory");
    }

    {
        const int r0 = wm * 16 + (lane >> 2);
        const int cbase = wn * 32 + (lane & 3) * 2;
#pragma unroll
        for (int nt = 0; nt < 4; nt++) {
            sL[(r0)     * 68 + cbase + nt * 8]     = acc[nt][0];
            sL[(r0)     * 68 + cbase + nt * 8 + 1] = acc[nt][1];
            sL[(r0 + 8) * 68 + cbase + nt * 8]     = acc[nt][2];
            sL[(r0 + 8) * 68 + cbase + nt * 8 + 1] = acc[nt][3];
        }
    }
    __syncthreads();

    {
        const int row = tid >> 2;
        const int cb = (tid & 3) * 16;
        float mx = -1e30f;
#pragma unroll
        for (int c = 0; c < 16; c++) mx = fmaxf(mx, sL[row * 68 + cb + c]);
        mx = fmaxf(mx, __shfl_xor_sync(0xffffffffu, mx, 1));
        mx = fmaxf(mx, __shfl_xor_sync(0xffffffffu, mx, 2));
        float ev[16];
        float sum = 0.0f;
#pragma unroll
        for (int c = 0; c < 16; c++) {
            ev[c] = __expf(sL[row * 68 + cb + c] - mx);
            sum += ev[c];
        }
        sum += __shfl_xor_sync(0xffffffffu, sum, 1);
        sum += __shfl_xor_sync(0xffffffffu, sum, 2);
        float inv = 1.0f / sum;
        __syncthreads();
#pragma unroll
        for (int c = 0; c < 8; c++) {
            uint32_t pk = packh2(ev[c * 2] * inv, ev[c * 2 + 1] * inv);
            *(uint32_t*)(sm + (row * 144 + (cb + c * 2) * 2)) = pk;
        }
    }
    __syncthreads();

    auto loadV = [&](int s, int ec) {
        const __half* vs = vb + (size_t)ldr * E_ + ec * 128 + ldc * 8;
        uint32_t d = (uint32_t)(ldr * 272 + ldc * 16);
#pragma unroll
        for (int jj = 0; jj < 4; jj++)
            cpasync16(sV[s] + d + jj * 64, vs + jj * 32);
        asm volatile("cp.async.commit_group;" ::: "memory");
    };

    loadV(0, 0);
    loadV(1, 1);

    const int wm2 = wid & 1;
    const int wn2 = wid >> 1;
    const int prow0 = wm2 * 32 + (lane & 15);
    const int vs0 = ((lane >> 3) & 1) * 8 + (lane & 7);
    const int ve0 = wn2 * 32 + (lane >> 4) * 8;

    for (int ec = 0; ec < 8; ec++) {
        const int cur = ec & 1;
        asm volatile("cp.async.wait_group 1;" ::: "memory");
        __syncthreads();

        float acc2[2][4][4];
#pragma unroll
        for (int i = 0; i < 2; i++)
#pragma unroll
            for (int j = 0; j < 4; j++)
#pragma unroll
                for (int f = 0; f < 4; f++) acc2[i][j][f] = 0.0f;

#pragma unroll
        for (int ks = 0; ks < 4; ks++) {
            uint32_t bf[2][4];
#pragma unroll
            for (int ntp = 0; ntp < 2; ntp++)
                ldmx4t(bf[ntp], sV[cur] + (uint32_t)((ks * 16 + vs0) * 272 +
                                                     (ve0 + ntp * 16) * 2));
#pragma unroll
            for (int mt = 0; mt < 2; mt++) {
                uint32_t af[4];
                ldmx4(af, sP + (uint32_t)((prow0 + mt * 16) * 144 +
                                          ks * 32 + acs * 16));
#pragma unroll
                for (int nt = 0; nt < 4; nt++)
                    mma_f16(acc2[mt][nt], af, bf[nt >> 1] + (nt & 1) * 2);
            }
        }

#pragma unroll
        for (int mt = 0; mt < 2; mt++) {
#pragma unroll
            for (int half = 0; half < 2; half++) {
                const int row = wm2 * 32 + mt * 16 + half * 8 + (lane >> 2);
#pragma unroll
                for (int nt = 0; nt < 4; nt++) {
                    const int col = ec * 128 + wn2 * 32 + nt * 8 + (lane & 3) * 2;
                    uint32_t o = packh2(acc2[mt][nt][half * 2],
                                        acc2[mt][nt][half * 2 + 1]);
                    *(uint32_t*)(yb + (size_t)row * HE_ + col) = o;
                }
            }
        }

        __syncthreads();
        if (ec + 2 < 8) loadV(cur, ec + 2);
        else asm volatile("cp.async.commit_group;" ::: "memory");
    }
}

// ---------------------------------------------------------------------------
extern "C" void kernel_launch(void* const* d_in, const int* in_sizes, int n_in,
                              void* d_out, int out_size)
{
    const float* x    = (const float*)d_in[0];
    const float* mask = (const float*)d_in[1];
    const float* Wq   = (const float*)d_in[2];
    const float* Wk   = (const float*)d_in[3];
    const float* Wv   = (const float*)d_in[4];
    const float* Wo   = (const float*)d_in[5];
    const float* bo   = (const float*)d_in[6];
    float* out = (float*)d_out;

    __half *qh, *kh, *vh, *yh, *xh, *wqkv, *woh;
    float *part;
    cudaGetSymbolAddress((void**)&qh, g_qh);
    cudaGetSymbolAddress((void**)&kh, g_kh);
    cudaGetSymbolAddress((void**)&vh, g_vh);
    cudaGetSymbolAddress((void**)&yh, g_y);
    cudaGetSymbolAddress((void**)&xh, g_xh);
    cudaGetSymbolAddress((void**)&wqkv, g_wqkv);
    cudaGetSymbolAddress((void**)&woh, g_woh);
    cudaGetSymbolAddress((void**)&part, g_part);

    const int SMEM = 2 * NSTAGE * TSTG;   // 65536
    static bool attr_set = false;
    if (!attr_set) {
        cudaFuncSetAttribute((const void*)gemm_f16<E_, E_, 0>,
                             cudaFuncAttributeMaxDynamicSharedMemorySize, SMEM);
        cudaFuncSetAttribute((const void*)gemm_f16<HE_, KSPL, 2>,
                             cudaFuncAttributeMaxDynamicSharedMemorySize, SMEM);
        cudaFuncSetAttribute(attn_fused_kernel,
                             cudaFuncAttributeMaxDynamicSharedMemorySize, ATT_SMEM);
        attr_set = true;
    }

    cvt_all_kernel<<<(CVT_TOT + 255) / 256, 256>>>(
        (const float4*)x, (const float4*)Wq, (const float4*)Wk,
        (const float4*)Wv, (const float4*)Wo,
        (uint2*)xh, (uint2*)wqkv, (uint2*)woh);

    dim3 g1(3 * HE_ / 128, M_ / 128);   // (192, 16)
    gemm_f16<E_, E_, 0><<<g1, 128, SMEM>>>(xh, wqkv, mask, qh, kh, vh);

    attn_fused_kernel<<<dim3(H_, B_), 256, ATT_SMEM>>>(qh, kh, vh, yh);

    dim3 g2(E_ / 128, M_ / 128, NSPLIT);   // (8, 16, 4) = 512 blocks
    gemm_f16<HE_, KSPL, 2><<<g2, 128, SMEM>>>(yh, woh, mask, part, nullptr, nullptr);

    reduce_kernel<<<(M_ * E_ / 4 + 255) / 256, 256>>>(
        (const float4*)part, bo, mask, (float4*)out);
}